// round 4
// baseline (speedup 1.0000x reference)
#include <cuda_runtime.h>
#include <math.h>

#define NIMG 32768
#define DIN  620

// 81.3 MB feature scratch (device global: allocation-free per harness rules)
__device__ float g_feat[(size_t)NIMG * DIN];

// ---------------------------------------------------------------------------
// Kernel A: per-image top-200 stable descending selection + feature build.
// Sort-free: histogram -> per-bin suffix counts -> exact stable rank of the
// ~205 candidates via within-bucket comparisons -> direct scatter by rank.
// 512 threads to halve the serial depth of the barrier-separated phases.
// ---------------------------------------------------------------------------
__global__ __launch_bounds__(512) void topk_feat_kernel(
    const float* __restrict__ images, const float* __restrict__ angles) {
  __shared__ unsigned int vbits[784];
  __shared__ unsigned int hist[256];
  __shared__ unsigned int above[256];     // # elements in buckets > q
  __shared__ unsigned int cursor[256];
  __shared__ unsigned long long bucketed[784];
  __shared__ unsigned int gsuf[33];       // suffix sums of 8-bin groups
  __shared__ int sT;

  const int b = blockIdx.x;
  const int tid = threadIdx.x;
  const float* img = images + (size_t)b * 784;
  float* fo = g_feat + (size_t)b * DIN;

  // Noise features (independent of the selection)
  if (tid < 10) {
    float a = angles[(size_t)b * 10 + tid];
    float sn, cs;
    sincosf(a, &sn, &cs);
    fo[600 + 2 * tid] = cs;
    fo[601 + 2 * tid] = sn;
  }

  if (tid < 256) {
    hist[tid] = 0u;
    cursor[tid] = 0u;
  }
  __syncthreads();

  // Pass 1: load values, histogram by 8-bit quantized bucket
  for (int i = tid; i < 784; i += 512) {
    float v = img[i];
    vbits[i] = __float_as_uint(v);
    int q = min(255, (int)(v * 256.0f));
    atomicAdd(&hist[q], 1u);
  }
  __syncthreads();

  // Pass 2a: warp 0 computes inclusive suffix sums over 8-bin groups
  if (tid < 32) {
    unsigned int g = 0;
#pragma unroll
    for (int j = 0; j < 8; j++) g += hist[tid * 8 + j];
    unsigned int suf = g;
#pragma unroll
    for (int d = 1; d < 32; d <<= 1) {
      unsigned int o = __shfl_down_sync(0xffffffffu, suf, d);
      if (tid + d < 32) suf += o;
    }
    gsuf[tid] = suf;       // count in bins >= tid*8
    if (tid == 0) gsuf[32] = 0u;
  }
  __syncthreads();

  // Pass 2b: per-bin "above" counts; detect threshold bin T
  if (tid < 256) {
    int g = tid >> 3;
    unsigned int a = gsuf[g + 1];
    int hi8 = g * 8 + 7;
    for (int q = tid + 1; q <= hi8; q++) a += hist[q];
    above[tid] = a;
    if (a < 200u && a + hist[tid] >= 200u) sT = tid;  // exactly one bin
  }
  __syncthreads();
  const int T = sT;

  // Pass 3: scatter candidates (q >= T) into bucket-grouped slots.
  for (int i = tid; i < 784; i += 512) {
    unsigned int vb = vbits[i];
    float v = __uint_as_float(vb);
    int q = min(255, (int)(v * 256.0f));
    if (q >= T) {
      unsigned int pos = above[q] + atomicAdd(&cursor[q], 1u);
      bucketed[pos] = ((unsigned long long)vb << 32) | (unsigned int)i;
    }
  }
  __syncthreads();

  // Pass 4: exact stable rank of each candidate; write features at rank.
  const int ncand = (int)(above[T] + hist[T]);
  for (int s = tid; s < ncand; s += 512) {
    unsigned long long e = bucketed[s];
    unsigned int vb = (unsigned int)(e >> 32);
    unsigned int idx = (unsigned int)(e & 0xffffffffu);
    float v = __uint_as_float(vb);
    int q = min(255, (int)(v * 256.0f));
    int lo = (int)above[q];
    int hi = lo + (int)hist[q];
    int rank = lo;
    for (int m = lo; m < hi; m++) {
      if (m == s) continue;
      unsigned long long me = bucketed[m];
      unsigned int mvb = (unsigned int)(me >> 32);
      unsigned int midx = (unsigned int)(me & 0xffffffffu);
      if (mvb > vb || (mvb == vb && midx < idx)) rank++;
    }
    if (rank < 200) {
      int r = (int)idx / 28;
      int c = (int)idx - r * 28;
      float cx = (c < 14) ? (float)(c - 14) : (float)(c - 13);
      float cy = (r < 14) ? (float)(14 - r) : (float)(13 - r);
      float vv = v;
      if (vv < 0.1f) { vv = 0.f; cx = 0.f; cy = 0.f; }
      fo[rank] = vv;
      fo[200 + 2 * rank] = cx;
      fo[201 + 2 * rank] = cy;
    }
  }
}

// ---------------------------------------------------------------------------
// Kernel B: fused 4-layer MLP + 2x2 Gram-Schmidt epilogue
// 64 rows/block (512 blocks), 384 threads, 4x4 micro-tile (24 tc x 16 tr).
// Activations k-major (stride 68): per-k inner loop = 1 LDG.128 + 1 LDS.128
// (broadcast) + 16 FMAs. Doubles resident warps vs the 8x4 tiling.
// ---------------------------------------------------------------------------
__global__ __launch_bounds__(384) void mlp_kernel(
    const float* __restrict__ W1, const float* __restrict__ b1,
    const float* __restrict__ W2, const float* __restrict__ b2,
    const float* __restrict__ W3, const float* __restrict__ b3,
    const float* __restrict__ W4, const float* __restrict__ b4,
    float* __restrict__ outp) {
  __shared__ __align__(16) float fbuf[31 * 68];  // k-major feat slab
  __shared__ __align__(16) float hbuf[96 * 68];  // k-major activations

  const int tid = threadIdx.x;
  const int tc = tid % 24;   // 24 col-groups x 4 cols = 96
  const int tr = tid / 24;   // 16 row-groups x 4 rows = 64
  const int row0 = blockIdx.x * 64;
  const float* fptr = g_feat + (size_t)row0 * DIN;

  float acc[4][4];
#pragma unroll
  for (int i = 0; i < 4; i++)
#pragma unroll
    for (int j = 0; j < 4; j++) acc[i][j] = 0.f;

  // ---- Layer 1: 620 -> 96, k streamed in 20 slabs of 31 ----
  for (int ks = 0; ks < 620; ks += 31) {
    __syncthreads();
    for (int idx = tid; idx < 64 * 31; idx += 384) {
      int r = idx / 31;
      int kk = idx - r * 31;
      fbuf[kk * 68 + r] = fptr[(size_t)r * DIN + ks + kk];
    }
    __syncthreads();
#pragma unroll 2
    for (int kk = 0; kk < 31; kk++) {
      float4 w = *(const float4*)(W1 + (size_t)(ks + kk) * 96 + tc * 4);
      float4 fa = *(const float4*)(&fbuf[kk * 68 + tr * 4]);
      float f[4] = {fa.x, fa.y, fa.z, fa.w};
      float wv[4] = {w.x, w.y, w.z, w.w};
#pragma unroll
      for (int i = 0; i < 4; i++)
#pragma unroll
        for (int j = 0; j < 4; j++) acc[i][j] = fmaf(f[i], wv[j], acc[i][j]);
    }
  }
  __syncthreads();
  {
    float4 bv = *(const float4*)(b1 + tc * 4);
    float bl[4] = {bv.x, bv.y, bv.z, bv.w};
#pragma unroll
    for (int j = 0; j < 4; j++) {
      float4 s0;
      s0.x = fmaxf(acc[0][j] + bl[j], 0.f);
      s0.y = fmaxf(acc[1][j] + bl[j], 0.f);
      s0.z = fmaxf(acc[2][j] + bl[j], 0.f);
      s0.w = fmaxf(acc[3][j] + bl[j], 0.f);
      *(float4*)(&hbuf[(tc * 4 + j) * 68 + tr * 4]) = s0;
    }
  }
  __syncthreads();

  // ---- Layers 2 & 3: 96 -> 96 (accumulate in regs, then overwrite hbuf) ----
  for (int layer = 0; layer < 2; layer++) {
    const float* W = layer ? W3 : W2;
    const float* bp = layer ? b3 : b2;
    float a2[4][4];
#pragma unroll
    for (int i = 0; i < 4; i++)
#pragma unroll
      for (int j = 0; j < 4; j++) a2[i][j] = 0.f;
#pragma unroll 2
    for (int k = 0; k < 96; k++) {
      float4 w = *(const float4*)(W + (size_t)k * 96 + tc * 4);
      float4 fa = *(const float4*)(&hbuf[k * 68 + tr * 4]);
      float f[4] = {fa.x, fa.y, fa.z, fa.w};
      float wv[4] = {w.x, w.y, w.z, w.w};
#pragma unroll
      for (int i = 0; i < 4; i++)
#pragma unroll
        for (int j = 0; j < 4; j++) a2[i][j] = fmaf(f[i], wv[j], a2[i][j]);
    }
    __syncthreads();  // all reads of hbuf complete before overwrite
    {
      float4 bv = *(const float4*)(bp + tc * 4);
      float bl[4] = {bv.x, bv.y, bv.z, bv.w};
#pragma unroll
      for (int j = 0; j < 4; j++) {
        float4 s0;
        s0.x = fmaxf(a2[0][j] + bl[j], 0.f);
        s0.y = fmaxf(a2[1][j] + bl[j], 0.f);
        s0.z = fmaxf(a2[2][j] + bl[j], 0.f);
        s0.w = fmaxf(a2[3][j] + bl[j], 0.f);
        *(float4*)(&hbuf[(tc * 4 + j) * 68 + tr * 4]) = s0;
      }
    }
    __syncthreads();
  }

  // ---- Layer 4 (96 -> 4) + Gram-Schmidt epilogue, one thread per row ----
  if (tid < 64) {
    float o0 = 0.f, o1 = 0.f, o2 = 0.f, o3 = 0.f;
#pragma unroll 4
    for (int k = 0; k < 96; k++) {
      float hv = hbuf[k * 68 + tid];
      float4 w = *(const float4*)(W4 + (size_t)k * 4);
      o0 = fmaf(hv, w.x, o0);
      o1 = fmaf(hv, w.y, o1);
      o2 = fmaf(hv, w.z, o2);
      o3 = fmaf(hv, w.w, o3);
    }
    float4 bv = *(const float4*)(b4);
    o0 += bv.x; o1 += bv.y; o2 += bv.z; o3 += bv.w;

    // gs = out^T: c0 = (o0,o1), c1 = (o2,o3)
    float n0 = 1.0f / sqrtf(o0 * o0 + o1 * o1);
    float e0x = o0 * n0, e0y = o1 * n0;
    float dt = e0x * o2 + e0y * o3;
    float u1x = o2 - dt * e0x, u1y = o3 - dt * e0y;
    float n1 = 1.0f / sqrtf(u1x * u1x + u1y * u1y);
    float e1x = u1x * n1, e1y = u1y * n1;
    float det = e0x * e1y - e1x * e0y;

    float* po = outp + (size_t)(row0 + tid) * 4;
    po[0] = e0x * det;  // q[0][0]*det
    po[1] = e1x;        // q[0][1]
    po[2] = e0y * det;  // q[1][0]*det
    po[3] = e1y;        // q[1][1]
  }
}

// ---------------------------------------------------------------------------
extern "C" void kernel_launch(void* const* d_in, const int* in_sizes, int n_in,
                              void* d_out, int out_size) {
  (void)in_sizes; (void)n_in; (void)out_size;
  const float* images = (const float*)d_in[0];
  const float* angles = (const float*)d_in[1];
  const float* W1 = (const float*)d_in[2];
  const float* b1 = (const float*)d_in[3];
  const float* W2 = (const float*)d_in[4];
  const float* b2 = (const float*)d_in[5];
  const float* W3 = (const float*)d_in[6];
  const float* b3 = (const float*)d_in[7];
  const float* W4 = (const float*)d_in[8];
  const float* b4 = (const float*)d_in[9];
  float* outp = (float*)d_out;

  topk_feat_kernel<<<NIMG, 512>>>(images, angles);
  mlp_kernel<<<NIMG / 64, 384>>>(W1, b1, W2, b2, W3, b3, W4, b4, outp);
}

// round 5
// speedup vs baseline: 1.1469x; 1.1469x over previous
#include <cuda_runtime.h>
#include <math.h>

#define NIMG 32768
#define DIN  620

// 81.3 MB feature scratch (device global: allocation-free per harness rules)
__device__ float g_feat[(size_t)NIMG * DIN];

// packed fp32x2 FMA: d = a*b + d (elementwise on 64-bit packed pairs)
__device__ __forceinline__ void ffma2(unsigned long long& d,
                                      unsigned long long a,
                                      unsigned long long b) {
  asm("fma.rn.f32x2 %0, %1, %2, %0;" : "+l"(d) : "l"(a), "l"(b));
}
__device__ __forceinline__ unsigned long long dup2(float w) {
  unsigned long long r;
  asm("mov.b64 %0, {%1, %1};" : "=l"(r) : "f"(w));
  return r;
}
__device__ __forceinline__ void unpack2(unsigned long long p, float& lo, float& hi) {
  asm("mov.b64 {%0, %1}, %2;" : "=f"(lo), "=f"(hi) : "l"(p));
}

// ---------------------------------------------------------------------------
// Kernel A: per-image top-200 stable descending selection + feature build.
// Sort-free: histogram -> per-bin suffix counts -> exact stable rank of the
// ~205 candidates via within-bucket comparisons -> direct scatter by rank.
// ---------------------------------------------------------------------------
__global__ __launch_bounds__(256) void topk_feat_kernel(
    const float* __restrict__ images, const float* __restrict__ angles) {
  __shared__ unsigned int vbits[784];
  __shared__ unsigned int hist[256];
  __shared__ unsigned int above[256];     // # elements in buckets > q
  __shared__ unsigned int cursor[256];
  __shared__ unsigned long long bucketed[784];
  __shared__ unsigned int gsuf[33];       // suffix sums of 8-bin groups
  __shared__ int sT;

  const int b = blockIdx.x;
  const int tid = threadIdx.x;
  const float* img = images + (size_t)b * 784;
  float* fo = g_feat + (size_t)b * DIN;

  // Noise features (independent of the selection)
  if (tid < 10) {
    float a = angles[(size_t)b * 10 + tid];
    float sn, cs;
    sincosf(a, &sn, &cs);
    fo[600 + 2 * tid] = cs;
    fo[601 + 2 * tid] = sn;
  }

  hist[tid] = 0u;
  cursor[tid] = 0u;
  __syncthreads();

  // Pass 1: load values, histogram by 8-bit quantized bucket
  for (int i = tid; i < 784; i += 256) {
    float v = img[i];
    vbits[i] = __float_as_uint(v);
    int q = min(255, (int)(v * 256.0f));
    atomicAdd(&hist[q], 1u);
  }
  __syncthreads();

  // Pass 2a: warp 0 computes inclusive suffix sums over 8-bin groups
  if (tid < 32) {
    unsigned int g = 0;
#pragma unroll
    for (int j = 0; j < 8; j++) g += hist[tid * 8 + j];
    unsigned int suf = g;
#pragma unroll
    for (int d = 1; d < 32; d <<= 1) {
      unsigned int o = __shfl_down_sync(0xffffffffu, suf, d);
      if (tid + d < 32) suf += o;
    }
    gsuf[tid] = suf;       // count in bins >= tid*8
    if (tid == 0) gsuf[32] = 0u;
  }
  __syncthreads();

  // Pass 2b: per-bin "above" counts; detect threshold bin T
  {
    int g = tid >> 3;
    unsigned int a = gsuf[g + 1];
    int hi8 = g * 8 + 7;
    for (int q = tid + 1; q <= hi8; q++) a += hist[q];
    above[tid] = a;
    if (a < 200u && a + hist[tid] >= 200u) sT = tid;  // exactly one bin
  }
  __syncthreads();
  const int T = sT;

  // Pass 3: scatter candidates (q >= T) into bucket-grouped slots.
  for (int i = tid; i < 784; i += 256) {
    unsigned int vb = vbits[i];
    float v = __uint_as_float(vb);
    int q = min(255, (int)(v * 256.0f));
    if (q >= T) {
      unsigned int pos = above[q] + atomicAdd(&cursor[q], 1u);
      bucketed[pos] = ((unsigned long long)vb << 32) | (unsigned int)i;
    }
  }
  __syncthreads();

  // Pass 4: exact stable rank of each candidate; write features at rank.
  const int ncand = (int)(above[T] + hist[T]);
  for (int s = tid; s < ncand; s += 256) {
    unsigned long long e = bucketed[s];
    unsigned int vb = (unsigned int)(e >> 32);
    unsigned int idx = (unsigned int)(e & 0xffffffffu);
    float v = __uint_as_float(vb);
    int q = min(255, (int)(v * 256.0f));
    int lo = (int)above[q];
    int hi = lo + (int)hist[q];
    int rank = lo;
    for (int m = lo; m < hi; m++) {
      if (m == s) continue;
      unsigned long long me = bucketed[m];
      unsigned int mvb = (unsigned int)(me >> 32);
      unsigned int midx = (unsigned int)(me & 0xffffffffu);
      if (mvb > vb || (mvb == vb && midx < idx)) rank++;
    }
    if (rank < 200) {
      int r = (int)idx / 28;
      int c = (int)idx - r * 28;
      float cx = (c < 14) ? (float)(c - 14) : (float)(c - 13);
      float cy = (r < 14) ? (float)(14 - r) : (float)(13 - r);
      float vv = v;
      if (vv < 0.1f) { vv = 0.f; cx = 0.f; cy = 0.f; }
      fo[rank] = vv;
      fo[200 + 2 * rank] = cx;
      fo[201 + 2 * rank] = cy;
    }
  }
}

// ---------------------------------------------------------------------------
// Kernel B: fused 4-layer MLP + 2x2 Gram-Schmidt epilogue
// 64 rows/block (512 blocks), 192 threads, 8x4 micro-tile via packed f32x2:
// per warp-k: 16 FFMA2 + 4 mov.b64 + 2 LDS.128 + 1 LDG.128 for 32 FMAs.
// Activations k-major (stride 68) so row-pair reads are packed b64 lanes.
// ---------------------------------------------------------------------------
__global__ __launch_bounds__(192) void mlp_kernel(
    const float* __restrict__ W1, const float* __restrict__ b1,
    const float* __restrict__ W2, const float* __restrict__ b2,
    const float* __restrict__ W3, const float* __restrict__ b3,
    const float* __restrict__ W4, const float* __restrict__ b4,
    float* __restrict__ outp) {
  __shared__ __align__(16) float fbuf[31 * 68];  // k-major feat slab
  __shared__ __align__(16) float hbuf[96 * 68];  // k-major activations

  const int tid = threadIdx.x;
  const int tc = tid % 24;   // 24 col-groups x 4 cols = 96
  const int tr = tid / 24;   // 8 row-groups  x 8 rows = 64
  const int row0 = blockIdx.x * 64;
  const float* fptr = g_feat + (size_t)row0 * DIN;

  // acc2[i2][j]: packed rows (2*i2, 2*i2+1) x col j
  unsigned long long acc2[4][4];
#pragma unroll
  for (int i = 0; i < 4; i++)
#pragma unroll
    for (int j = 0; j < 4; j++) acc2[i][j] = 0ULL;

  // ---- Layer 1: 620 -> 96, k streamed in 20 slabs of 31 ----
  for (int ks = 0; ks < 620; ks += 31) {
    __syncthreads();
    for (int idx = tid; idx < 64 * 31; idx += 192) {
      int r = idx / 31;
      int kk = idx - r * 31;
      fbuf[kk * 68 + r] = fptr[(size_t)r * DIN + ks + kk];
    }
    __syncthreads();
#pragma unroll 2
    for (int kk = 0; kk < 31; kk++) {
      float4 w = *(const float4*)(W1 + (size_t)(ks + kk) * 96 + tc * 4);
      ulonglong2 fa = *(const ulonglong2*)(&fbuf[kk * 68 + tr * 8]);
      ulonglong2 fb = *(const ulonglong2*)(&fbuf[kk * 68 + tr * 8 + 4]);
      unsigned long long f2[4] = {fa.x, fa.y, fb.x, fb.y};
      unsigned long long wd[4] = {dup2(w.x), dup2(w.y), dup2(w.z), dup2(w.w)};
#pragma unroll
      for (int i = 0; i < 4; i++)
#pragma unroll
        for (int j = 0; j < 4; j++) ffma2(acc2[i][j], f2[i], wd[j]);
    }
  }
  __syncthreads();
  {
    float4 bv = *(const float4*)(b1 + tc * 4);
    float bl[4] = {bv.x, bv.y, bv.z, bv.w};
#pragma unroll
    for (int j = 0; j < 4; j++) {
      float4 s0, s1;
      unpack2(acc2[0][j], s0.x, s0.y);
      unpack2(acc2[1][j], s0.z, s0.w);
      unpack2(acc2[2][j], s1.x, s1.y);
      unpack2(acc2[3][j], s1.z, s1.w);
      s0.x = fmaxf(s0.x + bl[j], 0.f); s0.y = fmaxf(s0.y + bl[j], 0.f);
      s0.z = fmaxf(s0.z + bl[j], 0.f); s0.w = fmaxf(s0.w + bl[j], 0.f);
      s1.x = fmaxf(s1.x + bl[j], 0.f); s1.y = fmaxf(s1.y + bl[j], 0.f);
      s1.z = fmaxf(s1.z + bl[j], 0.f); s1.w = fmaxf(s1.w + bl[j], 0.f);
      *(float4*)(&hbuf[(tc * 4 + j) * 68 + tr * 8]) = s0;
      *(float4*)(&hbuf[(tc * 4 + j) * 68 + tr * 8 + 4]) = s1;
    }
  }
  __syncthreads();

  // ---- Layers 2 & 3: 96 -> 96 (accumulate in regs, then overwrite hbuf) ----
  for (int layer = 0; layer < 2; layer++) {
    const float* W = layer ? W3 : W2;
    const float* bp = layer ? b3 : b2;
    unsigned long long a2[4][4];
#pragma unroll
    for (int i = 0; i < 4; i++)
#pragma unroll
      for (int j = 0; j < 4; j++) a2[i][j] = 0ULL;
#pragma unroll 2
    for (int k = 0; k < 96; k++) {
      float4 w = *(const float4*)(W + (size_t)k * 96 + tc * 4);
      ulonglong2 fa = *(const ulonglong2*)(&hbuf[k * 68 + tr * 8]);
      ulonglong2 fb = *(const ulonglong2*)(&hbuf[k * 68 + tr * 8 + 4]);
      unsigned long long f2[4] = {fa.x, fa.y, fb.x, fb.y};
      unsigned long long wd[4] = {dup2(w.x), dup2(w.y), dup2(w.z), dup2(w.w)};
#pragma unroll
      for (int i = 0; i < 4; i++)
#pragma unroll
        for (int j = 0; j < 4; j++) ffma2(a2[i][j], f2[i], wd[j]);
    }
    __syncthreads();  // all reads of hbuf complete before overwrite
    {
      float4 bv = *(const float4*)(bp + tc * 4);
      float bl[4] = {bv.x, bv.y, bv.z, bv.w};
#pragma unroll
      for (int j = 0; j < 4; j++) {
        float4 s0, s1;
        unpack2(a2[0][j], s0.x, s0.y);
        unpack2(a2[1][j], s0.z, s0.w);
        unpack2(a2[2][j], s1.x, s1.y);
        unpack2(a2[3][j], s1.z, s1.w);
        s0.x = fmaxf(s0.x + bl[j], 0.f); s0.y = fmaxf(s0.y + bl[j], 0.f);
        s0.z = fmaxf(s0.z + bl[j], 0.f); s0.w = fmaxf(s0.w + bl[j], 0.f);
        s1.x = fmaxf(s1.x + bl[j], 0.f); s1.y = fmaxf(s1.y + bl[j], 0.f);
        s1.z = fmaxf(s1.z + bl[j], 0.f); s1.w = fmaxf(s1.w + bl[j], 0.f);
        *(float4*)(&hbuf[(tc * 4 + j) * 68 + tr * 8]) = s0;
        *(float4*)(&hbuf[(tc * 4 + j) * 68 + tr * 8 + 4]) = s1;
      }
    }
    __syncthreads();
  }

  // ---- Layer 4 (96 -> 4) + Gram-Schmidt epilogue, one thread per row ----
  if (tid < 64) {
    float o0 = 0.f, o1 = 0.f, o2 = 0.f, o3 = 0.f;
#pragma unroll 4
    for (int k = 0; k < 96; k++) {
      float hv = hbuf[k * 68 + tid];
      float4 w = *(const float4*)(W4 + (size_t)k * 4);
      o0 = fmaf(hv, w.x, o0);
      o1 = fmaf(hv, w.y, o1);
      o2 = fmaf(hv, w.z, o2);
      o3 = fmaf(hv, w.w, o3);
    }
    float4 bv = *(const float4*)(b4);
    o0 += bv.x; o1 += bv.y; o2 += bv.z; o3 += bv.w;

    // gs = out^T: c0 = (o0,o1), c1 = (o2,o3)
    float n0 = 1.0f / sqrtf(o0 * o0 + o1 * o1);
    float e0x = o0 * n0, e0y = o1 * n0;
    float dt = e0x * o2 + e0y * o3;
    float u1x = o2 - dt * e0x, u1y = o3 - dt * e0y;
    float n1 = 1.0f / sqrtf(u1x * u1x + u1y * u1y);
    float e1x = u1x * n1, e1y = u1y * n1;
    float det = e0x * e1y - e1x * e0y;

    float* po = outp + (size_t)(row0 + tid) * 4;
    po[0] = e0x * det;  // q[0][0]*det
    po[1] = e1x;        // q[0][1]
    po[2] = e0y * det;  // q[1][0]*det
    po[3] = e1y;        // q[1][1]
  }
}

// ---------------------------------------------------------------------------
extern "C" void kernel_launch(void* const* d_in, const int* in_sizes, int n_in,
                              void* d_out, int out_size) {
  (void)in_sizes; (void)n_in; (void)out_size;
  const float* images = (const float*)d_in[0];
  const float* angles = (const float*)d_in[1];
  const float* W1 = (const float*)d_in[2];
  const float* b1 = (const float*)d_in[3];
  const float* W2 = (const float*)d_in[4];
  const float* b2 = (const float*)d_in[5];
  const float* W3 = (const float*)d_in[6];
  const float* b3 = (const float*)d_in[7];
  const float* W4 = (const float*)d_in[8];
  const float* b4 = (const float*)d_in[9];
  float* outp = (float*)d_out;

  topk_feat_kernel<<<NIMG, 256>>>(images, angles);
  mlp_kernel<<<NIMG / 64, 192>>>(W1, b1, W2, b2, W3, b3, W4, b4, outp);
}

// round 9
// speedup vs baseline: 1.4787x; 1.2893x over previous
#include <cuda_runtime.h>
#include <math.h>

#define NIMG 32768
#define KPAD 640
#define DIN  620

// ---- device scratch (allocation-free) ----
__device__ __align__(16) float g_feat[(size_t)NIMG * KPAD];
__device__ __align__(16) float g_W1h[KPAD * 96];
__device__ __align__(16) float g_W1l[KPAD * 96];
__device__ __align__(16) float g_W2h[96 * 96];
__device__ __align__(16) float g_W2l[96 * 96];
__device__ __align__(16) float g_W3h[96 * 96];
__device__ __align__(16) float g_W3l[96 * 96];

// ---- tf32 helpers ----
__device__ __forceinline__ unsigned tf32_bits(float x) {
  unsigned r;
  asm("cvt.rna.tf32.f32 %0, %1;" : "=r"(r) : "f"(x));
  return r;
}
__device__ __forceinline__ void tf32_split(float x, unsigned& hi, unsigned& lo) {
  hi = tf32_bits(x);
  lo = tf32_bits(x - __uint_as_float(hi));
}

// D += A*B  (m16n8k8, tf32 inputs, f32 accum)
__device__ __forceinline__ void mma_tf32(float* c, const unsigned* a,
                                         unsigned b0, unsigned b1) {
  asm volatile(
      "mma.sync.aligned.m16n8k8.row.col.f32.tf32.tf32.f32 "
      "{%0,%1,%2,%3}, {%4,%5,%6,%7}, {%8,%9}, {%0,%1,%2,%3};"
      : "+f"(c[0]), "+f"(c[1]), "+f"(c[2]), "+f"(c[3])
      : "r"(a[0]), "r"(a[1]), "r"(a[2]), "r"(a[3]), "r"(b0), "r"(b1));
}

// ---------------------------------------------------------------------------
// Kernel A: per-image top-200 stable descending selection + feature build
// (identical mechanics to the passing R3 version, plus zero pad to KPAD)
// ---------------------------------------------------------------------------
__global__ __launch_bounds__(256) void topk_feat_kernel(
    const float* __restrict__ images, const float* __restrict__ angles) {
  __shared__ unsigned int vbits[784];
  __shared__ unsigned int hist[256];
  __shared__ unsigned int above[256];
  __shared__ unsigned int cursor[256];
  __shared__ unsigned long long bucketed[784];
  __shared__ unsigned int gsuf[33];
  __shared__ int sT;

  const int b = blockIdx.x;
  const int tid = threadIdx.x;
  const float* img = images + (size_t)b * 784;
  float* fo = g_feat + (size_t)b * KPAD;

  if (tid < 10) {
    float a = angles[(size_t)b * 10 + tid];
    float sn, cs;
    sincosf(a, &sn, &cs);
    fo[600 + 2 * tid] = cs;
    fo[601 + 2 * tid] = sn;
  } else if (tid < 30) {
    fo[620 + (tid - 10)] = 0.f;  // pad k = 620..639
  }

  hist[tid] = 0u;
  cursor[tid] = 0u;
  __syncthreads();

  for (int i = tid; i < 784; i += 256) {
    float v = img[i];
    vbits[i] = __float_as_uint(v);
    int q = min(255, (int)(v * 256.0f));
    atomicAdd(&hist[q], 1u);
  }
  __syncthreads();

  if (tid < 32) {
    unsigned int g = 0;
#pragma unroll
    for (int j = 0; j < 8; j++) g += hist[tid * 8 + j];
    unsigned int suf = g;
#pragma unroll
    for (int d = 1; d < 32; d <<= 1) {
      unsigned int o = __shfl_down_sync(0xffffffffu, suf, d);
      if (tid + d < 32) suf += o;
    }
    gsuf[tid] = suf;
    if (tid == 0) gsuf[32] = 0u;
  }
  __syncthreads();

  {
    int g = tid >> 3;
    unsigned int a = gsuf[g + 1];
    int hi8 = g * 8 + 7;
    for (int q = tid + 1; q <= hi8; q++) a += hist[q];
    above[tid] = a;
    if (a < 200u && a + hist[tid] >= 200u) sT = tid;
  }
  __syncthreads();
  const int T = sT;

  for (int i = tid; i < 784; i += 256) {
    unsigned int vb = vbits[i];
    float v = __uint_as_float(vb);
    int q = min(255, (int)(v * 256.0f));
    if (q >= T) {
      unsigned int pos = above[q] + atomicAdd(&cursor[q], 1u);
      bucketed[pos] = ((unsigned long long)vb << 32) | (unsigned int)i;
    }
  }
  __syncthreads();

  const int ncand = (int)(above[T] + hist[T]);
  for (int s = tid; s < ncand; s += 256) {
    unsigned long long e = bucketed[s];
    unsigned int vb = (unsigned int)(e >> 32);
    unsigned int idx = (unsigned int)(e & 0xffffffffu);
    float v = __uint_as_float(vb);
    int q = min(255, (int)(v * 256.0f));
    int lo = (int)above[q];
    int hi = lo + (int)hist[q];
    int rank = lo;
    for (int m = lo; m < hi; m++) {
      if (m == s) continue;
      unsigned long long me = bucketed[m];
      unsigned int mvb = (unsigned int)(me >> 32);
      unsigned int midx = (unsigned int)(me & 0xffffffffu);
      if (mvb > vb || (mvb == vb && midx < idx)) rank++;
    }
    if (rank < 200) {
      int r = (int)idx / 28;
      int c = (int)idx - r * 28;
      float cx = (c < 14) ? (float)(c - 14) : (float)(c - 13);
      float cy = (r < 14) ? (float)(14 - r) : (float)(13 - r);
      float vv = v;
      if (vv < 0.1f) { vv = 0.f; cx = 0.f; cy = 0.f; }
      fo[rank] = vv;
      fo[200 + 2 * rank] = cx;
      fo[201 + 2 * rank] = cy;
    }
  }
}

// ---------------------------------------------------------------------------
// Weight prep: split W into tf32 hi/lo (stored as fp32), zero-pad W1 to KPAD
// ---------------------------------------------------------------------------
__global__ void prep_weights(const float* __restrict__ W1,
                             const float* __restrict__ W2,
                             const float* __restrict__ W3) {
  int k = blockIdx.x;   // 0..639
  int n = threadIdx.x;  // 0..95
  {
    float v = (k < DIN) ? W1[(size_t)k * 96 + n] : 0.f;
    unsigned h, l;
    tf32_split(v, h, l);
    g_W1h[k * 96 + n] = __uint_as_float(h);
    g_W1l[k * 96 + n] = __uint_as_float(l);
  }
  if (k < 96) {
    unsigned h, l;
    tf32_split(W2[(size_t)k * 96 + n], h, l);
    g_W2h[k * 96 + n] = __uint_as_float(h);
    g_W2l[k * 96 + n] = __uint_as_float(l);
    tf32_split(W3[(size_t)k * 96 + n], h, l);
    g_W3h[k * 96 + n] = __uint_as_float(h);
    g_W3l[k * 96 + n] = __uint_as_float(l);
  }
}

// ---------------------------------------------------------------------------
// Kernel B: 3xTF32 mma.sync MLP + Gram-Schmidt epilogue
// 512 blocks x 128 threads; warp = M64 x N24 (4 m16-tiles x 3 n8-tiles)
// ---------------------------------------------------------------------------
#define SA  0      // feat slab  [64][36]  (k-chunk of 32, fp32)
#define SBH 2304   // W hi slab  [32][100]
#define SBL 5504   // W lo slab  [32][100]
#define SH  8704   // activations [64][100]
#define SM_FLOATS 15104  // 60416 bytes

__global__ __launch_bounds__(128) void mlp_mma_kernel(
    const float* __restrict__ b1, const float* __restrict__ b2,
    const float* __restrict__ b3, const float* __restrict__ W4,
    const float* __restrict__ b4, float* __restrict__ outp) {
  extern __shared__ float sm[];
  const int tid = threadIdx.x;
  const int warp = tid >> 5;
  const int lane = tid & 31;
  const int g = lane >> 2;   // group id (0..7)
  const int tg = lane & 3;   // thread-in-group (0..3)
  const int nbase = warp * 24;
  const int row0 = blockIdx.x * 64;

  float c[3][4][4];
#pragma unroll
  for (int nt = 0; nt < 3; nt++)
#pragma unroll
    for (int mt = 0; mt < 4; mt++)
#pragma unroll
      for (int f = 0; f < 4; f++) c[nt][mt][f] = 0.f;

  // ================= layer 1: K = 640, 20 chunks of 32 =================
  for (int ch = 0; ch < 20; ch++) {
    __syncthreads();
    // feat slab: 64 rows x 32 k
#pragma unroll
    for (int i = 0; i < 4; i++) {
      int idx = tid + i * 128;
      int r = idx >> 3, q = idx & 7;
      float4 v = *(const float4*)(g_feat + (size_t)(row0 + r) * KPAD + ch * 32 + q * 4);
      *(float4*)(sm + SA + r * 36 + q * 4) = v;
    }
    // W1 hi/lo slab: 32 rows x 96 n
#pragma unroll
    for (int i = 0; i < 6; i++) {
      int idx = tid + i * 128;
      int r = idx / 24, q = idx % 24;
      *(float4*)(sm + SBH + r * 100 + q * 4) =
          *(const float4*)(g_W1h + (size_t)(ch * 32 + r) * 96 + q * 4);
      *(float4*)(sm + SBL + r * 100 + q * 4) =
          *(const float4*)(g_W1l + (size_t)(ch * 32 + r) * 96 + q * 4);
    }
    __syncthreads();

#pragma unroll
    for (int k8 = 0; k8 < 4; k8++) {
      int kb = k8 * 8;
      unsigned ah[4][4], al[4][4];
#pragma unroll
      for (int mt = 0; mt < 4; mt++) {
        int r = mt * 16 + g;
        tf32_split(sm[SA + r * 36 + kb + tg], ah[mt][0], al[mt][0]);
        tf32_split(sm[SA + (r + 8) * 36 + kb + tg], ah[mt][1], al[mt][1]);
        tf32_split(sm[SA + r * 36 + kb + tg + 4], ah[mt][2], al[mt][2]);
        tf32_split(sm[SA + (r + 8) * 36 + kb + tg + 4], ah[mt][3], al[mt][3]);
      }
#pragma unroll
      for (int nt = 0; nt < 3; nt++) {
        int nb = nbase + nt * 8;
        unsigned b0h = __float_as_uint(sm[SBH + (kb + tg) * 100 + nb + g]);
        unsigned b1h = __float_as_uint(sm[SBH + (kb + tg + 4) * 100 + nb + g]);
        unsigned b0l = __float_as_uint(sm[SBL + (kb + tg) * 100 + nb + g]);
        unsigned b1l = __float_as_uint(sm[SBL + (kb + tg + 4) * 100 + nb + g]);
#pragma unroll
        for (int mt = 0; mt < 4; mt++) {
          mma_tf32(c[nt][mt], ah[mt], b0h, b1h);
          mma_tf32(c[nt][mt], ah[mt], b0l, b1l);
          mma_tf32(c[nt][mt], al[mt], b0h, b1h);
        }
      }
    }
  }

  // layer-1 writeback: bias + relu -> sH
  __syncthreads();
#pragma unroll
  for (int nt = 0; nt < 3; nt++) {
#pragma unroll
    for (int mt = 0; mt < 4; mt++) {
      int col = nbase + nt * 8 + 2 * tg;
      int r0 = mt * 16 + g;
      float bb0 = __ldg(b1 + col), bb1 = __ldg(b1 + col + 1);
      sm[SH + r0 * 100 + col] = fmaxf(c[nt][mt][0] + bb0, 0.f);
      sm[SH + r0 * 100 + col + 1] = fmaxf(c[nt][mt][1] + bb1, 0.f);
      sm[SH + (r0 + 8) * 100 + col] = fmaxf(c[nt][mt][2] + bb0, 0.f);
      sm[SH + (r0 + 8) * 100 + col + 1] = fmaxf(c[nt][mt][3] + bb1, 0.f);
#pragma unroll
      for (int f = 0; f < 4; f++) c[nt][mt][f] = 0.f;
    }
  }
  __syncthreads();

  // ================= layers 2 & 3: K = 96, 3 chunks of 32 =================
#pragma unroll 1
  for (int L = 0; L < 2; L++) {
    const float* Wh = L ? g_W3h : g_W2h;
    const float* Wl = L ? g_W3l : g_W2l;
    const float* bias = L ? b3 : b2;

#pragma unroll 1
    for (int ch = 0; ch < 3; ch++) {
      __syncthreads();
#pragma unroll
      for (int i = 0; i < 6; i++) {
        int idx = tid + i * 128;
        int r = idx / 24, q = idx % 24;
        *(float4*)(sm + SBH + r * 100 + q * 4) =
            *(const float4*)(Wh + (size_t)(ch * 32 + r) * 96 + q * 4);
        *(float4*)(sm + SBL + r * 100 + q * 4) =
            *(const float4*)(Wl + (size_t)(ch * 32 + r) * 96 + q * 4);
      }
      __syncthreads();

#pragma unroll
      for (int k8 = 0; k8 < 4; k8++) {
        int kb = k8 * 8;           // within slab
        int ka = ch * 32 + kb;     // within sH
        unsigned ah[4][4], al[4][4];
#pragma unroll
        for (int mt = 0; mt < 4; mt++) {
          int r = mt * 16 + g;
          tf32_split(sm[SH + r * 100 + ka + tg], ah[mt][0], al[mt][0]);
          tf32_split(sm[SH + (r + 8) * 100 + ka + tg], ah[mt][1], al[mt][1]);
          tf32_split(sm[SH + r * 100 + ka + tg + 4], ah[mt][2], al[mt][2]);
          tf32_split(sm[SH + (r + 8) * 100 + ka + tg + 4], ah[mt][3], al[mt][3]);
        }
#pragma unroll
        for (int nt = 0; nt < 3; nt++) {
          int nb = nbase + nt * 8;
          unsigned b0h = __float_as_uint(sm[SBH + (kb + tg) * 100 + nb + g]);
          unsigned b1h = __float_as_uint(sm[SBH + (kb + tg + 4) * 100 + nb + g]);
          unsigned b0l = __float_as_uint(sm[SBL + (kb + tg) * 100 + nb + g]);
          unsigned b1l = __float_as_uint(sm[SBL + (kb + tg + 4) * 100 + nb + g]);
#pragma unroll
          for (int mt = 0; mt < 4; mt++) {
            mma_tf32(c[nt][mt], ah[mt], b0h, b1h);
            mma_tf32(c[nt][mt], ah[mt], b0l, b1l);
            mma_tf32(c[nt][mt], al[mt], b0h, b1h);
          }
        }
      }
    }

    // writeback (all reads of sH complete: C lives in regs)
    __syncthreads();
#pragma unroll
    for (int nt = 0; nt < 3; nt++) {
#pragma unroll
      for (int mt = 0; mt < 4; mt++) {
        int col = nbase + nt * 8 + 2 * tg;
        int r0 = mt * 16 + g;
        float bb0 = __ldg(bias + col), bb1 = __ldg(bias + col + 1);
        sm[SH + r0 * 100 + col] = fmaxf(c[nt][mt][0] + bb0, 0.f);
        sm[SH + r0 * 100 + col + 1] = fmaxf(c[nt][mt][1] + bb1, 0.f);
        sm[SH + (r0 + 8) * 100 + col] = fmaxf(c[nt][mt][2] + bb0, 0.f);
        sm[SH + (r0 + 8) * 100 + col + 1] = fmaxf(c[nt][mt][3] + bb1, 0.f);
#pragma unroll
        for (int f = 0; f < 4; f++) c[nt][mt][f] = 0.f;
      }
    }
    __syncthreads();
  }

  // ================= layer 4 (96 -> 4) + Gram-Schmidt =================
  if (tid < 64) {
    float o0 = 0.f, o1 = 0.f, o2 = 0.f, o3 = 0.f;
#pragma unroll 4
    for (int k = 0; k < 96; k++) {
      float hv = sm[SH + tid * 100 + k];
      float4 w = *(const float4*)(W4 + (size_t)k * 4);
      o0 = fmaf(hv, w.x, o0);
      o1 = fmaf(hv, w.y, o1);
      o2 = fmaf(hv, w.z, o2);
      o3 = fmaf(hv, w.w, o3);
    }
    float4 bv = *(const float4*)(b4);
    o0 += bv.x; o1 += bv.y; o2 += bv.z; o3 += bv.w;

    float n0 = 1.0f / sqrtf(o0 * o0 + o1 * o1);
    float e0x = o0 * n0, e0y = o1 * n0;
    float dt = e0x * o2 + e0y * o3;
    float u1x = o2 - dt * e0x, u1y = o3 - dt * e0y;
    float n1 = 1.0f / sqrtf(u1x * u1x + u1y * u1y);
    float e1x = u1x * n1, e1y = u1y * n1;
    float det = e0x * e1y - e1x * e0y;

    float* po = outp + (size_t)(row0 + tid) * 4;
    po[0] = e0x * det;
    po[1] = e1x;
    po[2] = e0y * det;
    po[3] = e1y;
  }
}

// ---------------------------------------------------------------------------
extern "C" void kernel_launch(void* const* d_in, const int* in_sizes, int n_in,
                              void* d_out, int out_size) {
  (void)in_sizes; (void)n_in; (void)out_size;
  const float* images = (const float*)d_in[0];
  const float* angles = (const float*)d_in[1];
  const float* W1 = (const float*)d_in[2];
  const float* b1 = (const float*)d_in[3];
  const float* W2 = (const float*)d_in[4];
  const float* b2 = (const float*)d_in[5];
  const float* W3 = (const float*)d_in[6];
  const float* b3 = (const float*)d_in[7];
  const float* W4 = (const float*)d_in[8];
  const float* b4 = (const float*)d_in[9];
  float* outp = (float*)d_out;

  cudaFuncSetAttribute(mlp_mma_kernel, cudaFuncAttributeMaxDynamicSharedMemorySize,
                       SM_FLOATS * 4);

  topk_feat_kernel<<<NIMG, 256>>>(images, angles);
  prep_weights<<<KPAD, 96>>>(W1, W2, W3);
  mlp_mma_kernel<<<NIMG / 64, 128, SM_FLOATS * 4>>>(b1, b2, b3, W4, b4, outp);
}

// round 10
// speedup vs baseline: 1.6888x; 1.1421x over previous
#include <cuda_runtime.h>
#include <math.h>

#define NIMG 32768
#define KPAD 640
#define DIN  620

// ---- device scratch (allocation-free) ----
__device__ __align__(16) float g_feat[(size_t)NIMG * KPAD];
__device__ __align__(16) float g_W1h[KPAD * 96];
__device__ __align__(16) float g_W1l[KPAD * 96];
__device__ __align__(16) float g_W2h[96 * 96];
__device__ __align__(16) float g_W2l[96 * 96];
__device__ __align__(16) float g_W3h[96 * 96];
__device__ __align__(16) float g_W3l[96 * 96];

// ---- tf32 helpers ----
__device__ __forceinline__ unsigned tf32_bits(float x) {
  unsigned r;
  asm("cvt.rna.tf32.f32 %0, %1;" : "=r"(r) : "f"(x));
  return r;
}
__device__ __forceinline__ void tf32_split(float x, unsigned& hi, unsigned& lo) {
  hi = tf32_bits(x);
  lo = tf32_bits(x - __uint_as_float(hi));
}

// D += A*B  (m16n8k8, tf32 inputs, f32 accum)
__device__ __forceinline__ void mma_tf32(float* c, const unsigned* a,
                                         unsigned b0, unsigned b1) {
  asm volatile(
      "mma.sync.aligned.m16n8k8.row.col.f32.tf32.tf32.f32 "
      "{%0,%1,%2,%3}, {%4,%5,%6,%7}, {%8,%9}, {%0,%1,%2,%3};"
      : "+f"(c[0]), "+f"(c[1]), "+f"(c[2]), "+f"(c[3])
      : "r"(a[0]), "r"(a[1]), "r"(a[2]), "r"(a[3]), "r"(b0), "r"(b1));
}

// ---------------------------------------------------------------------------
// Kernel A: per-image top-200 stable descending selection + feature build.
// Register-resident values: thread t owns pixels 4t..4t+3 (vectorized LDG),
// no vbits shared array, single quantization.
// ---------------------------------------------------------------------------
__global__ __launch_bounds__(256) void topk_feat_kernel(
    const float* __restrict__ images, const float* __restrict__ angles) {
  __shared__ unsigned int hist[256];
  __shared__ unsigned int above[256];
  __shared__ unsigned int cursor[256];
  __shared__ unsigned long long bucketed[784];
  __shared__ unsigned int gsuf[33];
  __shared__ int sT;

  const int b = blockIdx.x;
  const int tid = threadIdx.x;
  const float* img = images + (size_t)b * 784;
  float* fo = g_feat + (size_t)b * KPAD;

  if (tid < 10) {
    float a = angles[(size_t)b * 10 + tid];
    float sn, cs;
    sincosf(a, &sn, &cs);
    fo[600 + 2 * tid] = cs;
    fo[601 + 2 * tid] = sn;
  } else if (tid < 30) {
    fo[620 + (tid - 10)] = 0.f;  // pad k = 620..639
  }

  hist[tid] = 0u;
  cursor[tid] = 0u;
  __syncthreads();

  // Pass 1: 196 threads load float4, histogram; values stay in registers
  float va[4];
  int qa[4];
  if (tid < 196) {
    float4 v4 = *(const float4*)(img + tid * 4);
    va[0] = v4.x; va[1] = v4.y; va[2] = v4.z; va[3] = v4.w;
#pragma unroll
    for (int j = 0; j < 4; j++) {
      qa[j] = min(255, (int)(va[j] * 256.0f));
      atomicAdd(&hist[qa[j]], 1u);
    }
  }
  __syncthreads();

  // Pass 2a: warp 0 computes inclusive suffix sums over 8-bin groups
  if (tid < 32) {
    unsigned int g = 0;
#pragma unroll
    for (int j = 0; j < 8; j++) g += hist[tid * 8 + j];
    unsigned int suf = g;
#pragma unroll
    for (int d = 1; d < 32; d <<= 1) {
      unsigned int o = __shfl_down_sync(0xffffffffu, suf, d);
      if (tid + d < 32) suf += o;
    }
    gsuf[tid] = suf;
    if (tid == 0) gsuf[32] = 0u;
  }
  __syncthreads();

  // Pass 2b: per-bin "above" counts; detect threshold bin T
  {
    int g = tid >> 3;
    unsigned int a = gsuf[g + 1];
    int hi8 = g * 8 + 7;
    for (int q = tid + 1; q <= hi8; q++) a += hist[q];
    above[tid] = a;
    if (a < 200u && a + hist[tid] >= 200u) sT = tid;
  }
  __syncthreads();
  const int T = sT;

  // Pass 3: scatter candidates (q >= T) into bucket-grouped slots
  if (tid < 196) {
#pragma unroll
    for (int j = 0; j < 4; j++) {
      if (qa[j] >= T) {
        unsigned int pos = above[qa[j]] + atomicAdd(&cursor[qa[j]], 1u);
        bucketed[pos] = ((unsigned long long)__float_as_uint(va[j]) << 32) |
                        (unsigned int)(tid * 4 + j);
      }
    }
  }
  __syncthreads();

  // Pass 4: exact stable rank of each candidate; write features at rank
  const int ncand = (int)(above[T] + hist[T]);
  for (int s = tid; s < ncand; s += 256) {
    unsigned long long e = bucketed[s];
    unsigned int vb = (unsigned int)(e >> 32);
    unsigned int idx = (unsigned int)(e & 0xffffffffu);
    float v = __uint_as_float(vb);
    int q = min(255, (int)(v * 256.0f));
    int lo = (int)above[q];
    int hi = lo + (int)hist[q];
    int rank = lo;
    for (int m = lo; m < hi; m++) {
      if (m == s) continue;
      unsigned long long me = bucketed[m];
      unsigned int mvb = (unsigned int)(me >> 32);
      unsigned int midx = (unsigned int)(me & 0xffffffffu);
      if (mvb > vb || (mvb == vb && midx < idx)) rank++;
    }
    if (rank < 200) {
      int r = (int)idx / 28;
      int c = (int)idx - r * 28;
      float cx = (c < 14) ? (float)(c - 14) : (float)(c - 13);
      float cy = (r < 14) ? (float)(14 - r) : (float)(13 - r);
      float vv = v;
      if (vv < 0.1f) { vv = 0.f; cx = 0.f; cy = 0.f; }
      fo[rank] = vv;
      fo[200 + 2 * rank] = cx;
      fo[201 + 2 * rank] = cy;
    }
  }
}

// ---------------------------------------------------------------------------
// Weight prep: split W into tf32 hi/lo (stored as fp32), zero-pad W1 to KPAD
// ---------------------------------------------------------------------------
__global__ void prep_weights(const float* __restrict__ W1,
                             const float* __restrict__ W2,
                             const float* __restrict__ W3) {
  int k = blockIdx.x;   // 0..639
  int n = threadIdx.x;  // 0..95
  {
    float v = (k < DIN) ? W1[(size_t)k * 96 + n] : 0.f;
    unsigned h, l;
    tf32_split(v, h, l);
    g_W1h[k * 96 + n] = __uint_as_float(h);
    g_W1l[k * 96 + n] = __uint_as_float(l);
  }
  if (k < 96) {
    unsigned h, l;
    tf32_split(W2[(size_t)k * 96 + n], h, l);
    g_W2h[k * 96 + n] = __uint_as_float(h);
    g_W2l[k * 96 + n] = __uint_as_float(l);
    tf32_split(W3[(size_t)k * 96 + n], h, l);
    g_W3h[k * 96 + n] = __uint_as_float(h);
    g_W3l[k * 96 + n] = __uint_as_float(l);
  }
}

// ---------------------------------------------------------------------------
// Kernel B: 3xTF32 mma.sync MLP + Gram-Schmidt epilogue
// 512 blocks x 256 threads (8 warps); warp = M32 x N24 (2 m16 x 3 n8 tiles)
// ---------------------------------------------------------------------------
#define SA  0      // feat slab  [64][36]  (k-chunk of 32, fp32)
#define SBH 2304   // W hi slab  [32][100]
#define SBL 5504   // W lo slab  [32][100]
#define SH  8704   // activations [64][100]
#define SM_FLOATS 15104  // 60416 bytes

__global__ __launch_bounds__(256) void mlp_mma_kernel(
    const float* __restrict__ b1, const float* __restrict__ b2,
    const float* __restrict__ b3, const float* __restrict__ W4,
    const float* __restrict__ b4, float* __restrict__ outp) {
  extern __shared__ float sm[];
  const int tid = threadIdx.x;
  const int warp = tid >> 5;
  const int lane = tid & 31;
  const int g = lane >> 2;   // group id (0..7)
  const int tg = lane & 3;   // thread-in-group (0..3)
  const int nbase = (warp & 3) * 24;   // n group
  const int mbase = (warp >> 2) * 32;  // m half
  const int row0 = blockIdx.x * 64;

  float c[3][2][4];
#pragma unroll
  for (int nt = 0; nt < 3; nt++)
#pragma unroll
    for (int mt = 0; mt < 2; mt++)
#pragma unroll
      for (int f = 0; f < 4; f++) c[nt][mt][f] = 0.f;

  // ================= layer 1: K = 640, 20 chunks of 32 =================
  for (int ch = 0; ch < 20; ch++) {
    __syncthreads();
    // feat slab: 64 rows x 32 k = 512 float4
#pragma unroll
    for (int i = 0; i < 2; i++) {
      int idx = tid + i * 256;
      int r = idx >> 3, q = idx & 7;
      float4 v = *(const float4*)(g_feat + (size_t)(row0 + r) * KPAD + ch * 32 + q * 4);
      *(float4*)(sm + SA + r * 36 + q * 4) = v;
    }
    // W1 hi/lo slab: 32 rows x 96 n = 768 float4 each
#pragma unroll
    for (int i = 0; i < 3; i++) {
      int idx = tid + i * 256;
      int r = idx / 24, q = idx % 24;
      *(float4*)(sm + SBH + r * 100 + q * 4) =
          *(const float4*)(g_W1h + (size_t)(ch * 32 + r) * 96 + q * 4);
      *(float4*)(sm + SBL + r * 100 + q * 4) =
          *(const float4*)(g_W1l + (size_t)(ch * 32 + r) * 96 + q * 4);
    }
    __syncthreads();

#pragma unroll
    for (int k8 = 0; k8 < 4; k8++) {
      int kb = k8 * 8;
      unsigned ah[2][4], al[2][4];
#pragma unroll
      for (int mt = 0; mt < 2; mt++) {
        int r = mbase + mt * 16 + g;
        tf32_split(sm[SA + r * 36 + kb + tg], ah[mt][0], al[mt][0]);
        tf32_split(sm[SA + (r + 8) * 36 + kb + tg], ah[mt][1], al[mt][1]);
        tf32_split(sm[SA + r * 36 + kb + tg + 4], ah[mt][2], al[mt][2]);
        tf32_split(sm[SA + (r + 8) * 36 + kb + tg + 4], ah[mt][3], al[mt][3]);
      }
#pragma unroll
      for (int nt = 0; nt < 3; nt++) {
        int nb = nbase + nt * 8;
        unsigned b0h = __float_as_uint(sm[SBH + (kb + tg) * 100 + nb + g]);
        unsigned b1h = __float_as_uint(sm[SBH + (kb + tg + 4) * 100 + nb + g]);
        unsigned b0l = __float_as_uint(sm[SBL + (kb + tg) * 100 + nb + g]);
        unsigned b1l = __float_as_uint(sm[SBL + (kb + tg + 4) * 100 + nb + g]);
#pragma unroll
        for (int mt = 0; mt < 2; mt++) {
          mma_tf32(c[nt][mt], ah[mt], b0h, b1h);
          mma_tf32(c[nt][mt], ah[mt], b0l, b1l);
          mma_tf32(c[nt][mt], al[mt], b0h, b1h);
        }
      }
    }
  }

  // layer-1 writeback: bias + relu -> sH
  __syncthreads();
#pragma unroll
  for (int nt = 0; nt < 3; nt++) {
#pragma unroll
    for (int mt = 0; mt < 2; mt++) {
      int col = nbase + nt * 8 + 2 * tg;
      int r0 = mbase + mt * 16 + g;
      float bb0 = __ldg(b1 + col), bb1 = __ldg(b1 + col + 1);
      sm[SH + r0 * 100 + col] = fmaxf(c[nt][mt][0] + bb0, 0.f);
      sm[SH + r0 * 100 + col + 1] = fmaxf(c[nt][mt][1] + bb1, 0.f);
      sm[SH + (r0 + 8) * 100 + col] = fmaxf(c[nt][mt][2] + bb0, 0.f);
      sm[SH + (r0 + 8) * 100 + col + 1] = fmaxf(c[nt][mt][3] + bb1, 0.f);
#pragma unroll
      for (int f = 0; f < 4; f++) c[nt][mt][f] = 0.f;
    }
  }
  __syncthreads();

  // ================= layers 2 & 3: K = 96, 3 chunks of 32 =================
#pragma unroll 1
  for (int L = 0; L < 2; L++) {
    const float* Wh = L ? g_W3h : g_W2h;
    const float* Wl = L ? g_W3l : g_W2l;
    const float* bias = L ? b3 : b2;

#pragma unroll 1
    for (int ch = 0; ch < 3; ch++) {
      __syncthreads();
#pragma unroll
      for (int i = 0; i < 3; i++) {
        int idx = tid + i * 256;
        int r = idx / 24, q = idx % 24;
        *(float4*)(sm + SBH + r * 100 + q * 4) =
            *(const float4*)(Wh + (size_t)(ch * 32 + r) * 96 + q * 4);
        *(float4*)(sm + SBL + r * 100 + q * 4) =
            *(const float4*)(Wl + (size_t)(ch * 32 + r) * 96 + q * 4);
      }
      __syncthreads();

#pragma unroll
      for (int k8 = 0; k8 < 4; k8++) {
        int kb = k8 * 8;           // within slab
        int ka = ch * 32 + kb;     // within sH
        unsigned ah[2][4], al[2][4];
#pragma unroll
        for (int mt = 0; mt < 2; mt++) {
          int r = mbase + mt * 16 + g;
          tf32_split(sm[SH + r * 100 + ka + tg], ah[mt][0], al[mt][0]);
          tf32_split(sm[SH + (r + 8) * 100 + ka + tg], ah[mt][1], al[mt][1]);
          tf32_split(sm[SH + r * 100 + ka + tg + 4], ah[mt][2], al[mt][2]);
          tf32_split(sm[SH + (r + 8) * 100 + ka + tg + 4], ah[mt][3], al[mt][3]);
        }
#pragma unroll
        for (int nt = 0; nt < 3; nt++) {
          int nb = nbase + nt * 8;
          unsigned b0h = __float_as_uint(sm[SBH + (kb + tg) * 100 + nb + g]);
          unsigned b1h = __float_as_uint(sm[SBH + (kb + tg + 4) * 100 + nb + g]);
          unsigned b0l = __float_as_uint(sm[SBL + (kb + tg) * 100 + nb + g]);
          unsigned b1l = __float_as_uint(sm[SBL + (kb + tg + 4) * 100 + nb + g]);
#pragma unroll
          for (int mt = 0; mt < 2; mt++) {
            mma_tf32(c[nt][mt], ah[mt], b0h, b1h);
            mma_tf32(c[nt][mt], ah[mt], b0l, b1l);
            mma_tf32(c[nt][mt], al[mt], b0h, b1h);
          }
        }
      }
    }

    // writeback (all reads of sH complete before overwrite)
    __syncthreads();
#pragma unroll
    for (int nt = 0; nt < 3; nt++) {
#pragma unroll
      for (int mt = 0; mt < 2; mt++) {
        int col = nbase + nt * 8 + 2 * tg;
        int r0 = mbase + mt * 16 + g;
        float bb0 = __ldg(bias + col), bb1 = __ldg(bias + col + 1);
        sm[SH + r0 * 100 + col] = fmaxf(c[nt][mt][0] + bb0, 0.f);
        sm[SH + r0 * 100 + col + 1] = fmaxf(c[nt][mt][1] + bb1, 0.f);
        sm[SH + (r0 + 8) * 100 + col] = fmaxf(c[nt][mt][2] + bb0, 0.f);
        sm[SH + (r0 + 8) * 100 + col + 1] = fmaxf(c[nt][mt][3] + bb1, 0.f);
#pragma unroll
        for (int f = 0; f < 4; f++) c[nt][mt][f] = 0.f;
      }
    }
    __syncthreads();
  }

  // ================= layer 4 (96 -> 4) + Gram-Schmidt =================
  if (tid < 64) {
    float o0 = 0.f, o1 = 0.f, o2 = 0.f, o3 = 0.f;
#pragma unroll 4
    for (int k = 0; k < 96; k++) {
      float hv = sm[SH + tid * 100 + k];
      float4 w = *(const float4*)(W4 + (size_t)k * 4);
      o0 = fmaf(hv, w.x, o0);
      o1 = fmaf(hv, w.y, o1);
      o2 = fmaf(hv, w.z, o2);
      o3 = fmaf(hv, w.w, o3);
    }
    float4 bv = *(const float4*)(b4);
    o0 += bv.x; o1 += bv.y; o2 += bv.z; o3 += bv.w;

    float n0 = 1.0f / sqrtf(o0 * o0 + o1 * o1);
    float e0x = o0 * n0, e0y = o1 * n0;
    float dt = e0x * o2 + e0y * o3;
    float u1x = o2 - dt * e0x, u1y = o3 - dt * e0y;
    float n1 = 1.0f / sqrtf(u1x * u1x + u1y * u1y);
    float e1x = u1x * n1, e1y = u1y * n1;
    float det = e0x * e1y - e1x * e0y;

    float* po = outp + (size_t)(row0 + tid) * 4;
    po[0] = e0x * det;
    po[1] = e1x;
    po[2] = e0y * det;
    po[3] = e1y;
  }
}

// ---------------------------------------------------------------------------
extern "C" void kernel_launch(void* const* d_in, const int* in_sizes, int n_in,
                              void* d_out, int out_size) {
  (void)in_sizes; (void)n_in; (void)out_size;
  const float* images = (const float*)d_in[0];
  const float* angles = (const float*)d_in[1];
  const float* W1 = (const float*)d_in[2];
  const float* b1 = (const float*)d_in[3];
  const float* W2 = (const float*)d_in[4];
  const float* b2 = (const float*)d_in[5];
  const float* W3 = (const float*)d_in[6];
  const float* b3 = (const float*)d_in[7];
  const float* W4 = (const float*)d_in[8];
  const float* b4 = (const float*)d_in[9];
  float* outp = (float*)d_out;

  cudaFuncSetAttribute(mlp_mma_kernel, cudaFuncAttributeMaxDynamicSharedMemorySize,
                       SM_FLOATS * 4);

  topk_feat_kernel<<<NIMG, 256>>>(images, angles);
  prep_weights<<<KPAD, 96>>>(W1, W2, W3);
  mlp_mma_kernel<<<NIMG / 64, 256, SM_FLOATS * 4>>>(b1, b2, b3, W4, b4, outp);
}

// round 11
// speedup vs baseline: 1.7284x; 1.0234x over previous
#include <cuda_runtime.h>
#include <math.h>

#define NIMG 32768
#define KPAD 640
#define DIN  620

// ---- device scratch (allocation-free) ----
__device__ __align__(16) float g_feat[(size_t)NIMG * KPAD];
__device__ __align__(16) float g_W1h[KPAD * 96];
__device__ __align__(16) float g_W1l[KPAD * 96];
__device__ __align__(16) float g_W2h[96 * 96];
__device__ __align__(16) float g_W2l[96 * 96];
__device__ __align__(16) float g_W3h[96 * 96];
__device__ __align__(16) float g_W3l[96 * 96];

// ---- tf32 helpers ----
__device__ __forceinline__ unsigned tf32_bits(float x) {
  unsigned r;
  asm("cvt.rna.tf32.f32 %0, %1;" : "=r"(r) : "f"(x));
  return r;
}
__device__ __forceinline__ void tf32_split(float x, unsigned& hi, unsigned& lo) {
  hi = tf32_bits(x);
  lo = tf32_bits(x - __uint_as_float(hi));
}

// D += A*B  (m16n8k8, tf32 inputs, f32 accum)
__device__ __forceinline__ void mma_tf32(float* c, const unsigned* a,
                                         unsigned b0, unsigned b1) {
  asm volatile(
      "mma.sync.aligned.m16n8k8.row.col.f32.tf32.tf32.f32 "
      "{%0,%1,%2,%3}, {%4,%5,%6,%7}, {%8,%9}, {%0,%1,%2,%3};"
      : "+f"(c[0]), "+f"(c[1]), "+f"(c[2]), "+f"(c[3])
      : "r"(a[0]), "r"(a[1]), "r"(a[2]), "r"(a[3]), "r"(b0), "r"(b1));
}

__device__ __forceinline__ unsigned smem_u32(const void* p) {
  unsigned a;
  asm("{ .reg .u64 t; cvta.to.shared.u64 t, %1; cvt.u32.u64 %0, t; }" : "=r"(a) : "l"(p));
  return a;
}
__device__ __forceinline__ void cp16(unsigned dst, const void* src) {
  asm volatile("cp.async.ca.shared.global [%0], [%1], 16;" :: "r"(dst), "l"(src));
}
#define CP_COMMIT() asm volatile("cp.async.commit_group;" ::: "memory")
#define CP_WAIT0()  asm volatile("cp.async.wait_group 0;" ::: "memory")

// ---------------------------------------------------------------------------
// Kernel A: per-image top-200 stable selection + feature build.
// Values register-resident; features staged in smem, flushed coalesced.
// ---------------------------------------------------------------------------
__global__ __launch_bounds__(256) void topk_feat_kernel(
    const float* __restrict__ images, const float* __restrict__ angles) {
  __shared__ unsigned int hist[256];
  __shared__ unsigned int above[256];
  __shared__ unsigned int cursor[256];
  __shared__ unsigned long long bucketed[784];
  __shared__ unsigned int gsuf[33];
  __shared__ __align__(16) float sfeat[640];
  __shared__ int sT;

  const int b = blockIdx.x;
  const int tid = threadIdx.x;
  const float* img = images + (size_t)b * 784;
  float* fo = g_feat + (size_t)b * KPAD;

  if (tid < 10) {
    float a = angles[(size_t)b * 10 + tid];
    float sn, cs;
    sincosf(a, &sn, &cs);
    sfeat[600 + 2 * tid] = cs;
    sfeat[601 + 2 * tid] = sn;
  } else if (tid < 30) {
    sfeat[620 + (tid - 10)] = 0.f;  // pad k = 620..639
  }

  hist[tid] = 0u;
  cursor[tid] = 0u;
  __syncthreads();

  // Pass 1: 196 threads load float4, histogram; values stay in registers
  float va[4];
  int qa[4];
  if (tid < 196) {
    float4 v4 = *(const float4*)(img + tid * 4);
    va[0] = v4.x; va[1] = v4.y; va[2] = v4.z; va[3] = v4.w;
#pragma unroll
    for (int j = 0; j < 4; j++) {
      qa[j] = min(255, (int)(va[j] * 256.0f));
      atomicAdd(&hist[qa[j]], 1u);
    }
  }
  __syncthreads();

  // Pass 2a: warp 0 computes inclusive suffix sums over 8-bin groups
  if (tid < 32) {
    unsigned int g = 0;
#pragma unroll
    for (int j = 0; j < 8; j++) g += hist[tid * 8 + j];
    unsigned int suf = g;
#pragma unroll
    for (int d = 1; d < 32; d <<= 1) {
      unsigned int o = __shfl_down_sync(0xffffffffu, suf, d);
      if (tid + d < 32) suf += o;
    }
    gsuf[tid] = suf;
    if (tid == 0) gsuf[32] = 0u;
  }
  __syncthreads();

  // Pass 2b: per-bin "above" counts; detect threshold bin T
  {
    int g = tid >> 3;
    unsigned int a = gsuf[g + 1];
    int hi8 = g * 8 + 7;
    for (int q = tid + 1; q <= hi8; q++) a += hist[q];
    above[tid] = a;
    if (a < 200u && a + hist[tid] >= 200u) sT = tid;
  }
  __syncthreads();
  const int T = sT;

  // Pass 3: scatter candidates (q >= T) into bucket-grouped slots
  if (tid < 196) {
#pragma unroll
    for (int j = 0; j < 4; j++) {
      if (qa[j] >= T) {
        unsigned int pos = above[qa[j]] + atomicAdd(&cursor[qa[j]], 1u);
        bucketed[pos] = ((unsigned long long)__float_as_uint(va[j]) << 32) |
                        (unsigned int)(tid * 4 + j);
      }
    }
  }
  __syncthreads();

  // Pass 4: exact stable rank; write features into smem staging
  const int ncand = (int)(above[T] + hist[T]);
  for (int s = tid; s < ncand; s += 256) {
    unsigned long long e = bucketed[s];
    unsigned int vb = (unsigned int)(e >> 32);
    unsigned int idx = (unsigned int)(e & 0xffffffffu);
    float v = __uint_as_float(vb);
    int q = min(255, (int)(v * 256.0f));
    int lo = (int)above[q];
    int hi = lo + (int)hist[q];
    int rank = lo;
    for (int m = lo; m < hi; m++) {
      if (m == s) continue;
      unsigned long long me = bucketed[m];
      unsigned int mvb = (unsigned int)(me >> 32);
      unsigned int midx = (unsigned int)(me & 0xffffffffu);
      if (mvb > vb || (mvb == vb && midx < idx)) rank++;
    }
    if (rank < 200) {
      int r = (int)idx / 28;
      int c = (int)idx - r * 28;
      float cx = (c < 14) ? (float)(c - 14) : (float)(c - 13);
      float cy = (r < 14) ? (float)(14 - r) : (float)(13 - r);
      float vv = v;
      if (vv < 0.1f) { vv = 0.f; cx = 0.f; cy = 0.f; }
      sfeat[rank] = vv;
      sfeat[200 + 2 * rank] = cx;
      sfeat[201 + 2 * rank] = cy;
    }
  }
  __syncthreads();

  // Coalesced flush: 640 floats = 160 float4
  if (tid < 160) {
    ((float4*)fo)[tid] = ((const float4*)sfeat)[tid];
  }
}

// ---------------------------------------------------------------------------
// Weight prep: split W into tf32 hi/lo (stored as fp32), zero-pad W1 to KPAD
// ---------------------------------------------------------------------------
__global__ void prep_weights(const float* __restrict__ W1,
                             const float* __restrict__ W2,
                             const float* __restrict__ W3) {
  int k = blockIdx.x;   // 0..639
  int n = threadIdx.x;  // 0..95
  {
    float v = (k < DIN) ? W1[(size_t)k * 96 + n] : 0.f;
    unsigned h, l;
    tf32_split(v, h, l);
    g_W1h[k * 96 + n] = __uint_as_float(h);
    g_W1l[k * 96 + n] = __uint_as_float(l);
  }
  if (k < 96) {
    unsigned h, l;
    tf32_split(W2[(size_t)k * 96 + n], h, l);
    g_W2h[k * 96 + n] = __uint_as_float(h);
    g_W2l[k * 96 + n] = __uint_as_float(l);
    tf32_split(W3[(size_t)k * 96 + n], h, l);
    g_W3h[k * 96 + n] = __uint_as_float(h);
    g_W3l[k * 96 + n] = __uint_as_float(l);
  }
}

// ---------------------------------------------------------------------------
// Kernel B: 3xTF32 mma.sync MLP + Gram-Schmidt epilogue
// 512 blocks x 256 threads (8 warps); warp = M32 x N24 (2 m16 x 3 n8 tiles).
// A pre-split into SAH/SAL at load time (once, not per-warp); feat register-
// prefetched; W slabs via cp.async.
// ---------------------------------------------------------------------------
#define SAH 0       // A hi slab [64][36]
#define SAL 2304    // A lo slab [64][36]
#define SBH 4608    // W hi slab [32][100]
#define SBL 7808    // W lo slab [32][100]
#define SH  11008   // activations [64][100] fp32
#define SM_FLOATS 17408  // 69632 bytes

__global__ __launch_bounds__(256) void mlp_mma_kernel(
    const float* __restrict__ b1, const float* __restrict__ b2,
    const float* __restrict__ b3, const float* __restrict__ W4,
    const float* __restrict__ b4, float* __restrict__ outp) {
  extern __shared__ float sm[];
  const unsigned smb = smem_u32(sm);
  const int tid = threadIdx.x;
  const int warp = tid >> 5;
  const int lane = tid & 31;
  const int g = lane >> 2;
  const int tg = lane & 3;
  const int nbase = (warp & 3) * 24;
  const int mbase = (warp >> 2) * 32;
  const int row0 = blockIdx.x * 64;

  // per-thread A-slab coordinates (2 float4 per thread, 64x32 slab)
  const int ar0 = tid >> 3, aq0 = tid & 7;
  const int ar1 = (tid + 256) >> 3, aq1 = (tid + 256) & 7;
  // per-thread W-slab coordinates (3 float4 per thread, 32x96 slab)
  const int wr0 = tid / 24, wq0 = tid % 24;
  const int wr1 = (tid + 256) / 24, wq1 = (tid + 256) % 24;
  const int wr2 = (tid + 512) / 24, wq2 = (tid + 512) % 24;

  float c[3][2][4];
#pragma unroll
  for (int nt = 0; nt < 3; nt++)
#pragma unroll
    for (int mt = 0; mt < 2; mt++)
#pragma unroll
      for (int f = 0; f < 4; f++) c[nt][mt][f] = 0.f;

  // prefetch feat chunk 0
  float4 pfA0 = *(const float4*)(g_feat + (size_t)(row0 + ar0) * KPAD + aq0 * 4);
  float4 pfA1 = *(const float4*)(g_feat + (size_t)(row0 + ar1) * KPAD + aq1 * 4);

  // ================= layer 1: K = 640, 20 chunks of 32 =================
  for (int ch = 0; ch < 20; ch++) {
    __syncthreads();  // stage consumers done
    // W slabs via cp.async
    cp16(smb + (SBH + wr0 * 100 + wq0 * 4) * 4, g_W1h + (size_t)(ch * 32 + wr0) * 96 + wq0 * 4);
    cp16(smb + (SBL + wr0 * 100 + wq0 * 4) * 4, g_W1l + (size_t)(ch * 32 + wr0) * 96 + wq0 * 4);
    cp16(smb + (SBH + wr1 * 100 + wq1 * 4) * 4, g_W1h + (size_t)(ch * 32 + wr1) * 96 + wq1 * 4);
    cp16(smb + (SBL + wr1 * 100 + wq1 * 4) * 4, g_W1l + (size_t)(ch * 32 + wr1) * 96 + wq1 * 4);
    cp16(smb + (SBH + wr2 * 100 + wq2 * 4) * 4, g_W1h + (size_t)(ch * 32 + wr2) * 96 + wq2 * 4);
    cp16(smb + (SBL + wr2 * 100 + wq2 * 4) * 4, g_W1l + (size_t)(ch * 32 + wr2) * 96 + wq2 * 4);
    CP_COMMIT();

    // A: split prefetched regs -> SAH/SAL
    {
      float v0[4] = {pfA0.x, pfA0.y, pfA0.z, pfA0.w};
      float v1[4] = {pfA1.x, pfA1.y, pfA1.z, pfA1.w};
      float h0[4], l0[4], h1[4], l1[4];
#pragma unroll
      for (int j = 0; j < 4; j++) {
        unsigned h, l;
        tf32_split(v0[j], h, l);
        h0[j] = __uint_as_float(h); l0[j] = __uint_as_float(l);
        tf32_split(v1[j], h, l);
        h1[j] = __uint_as_float(h); l1[j] = __uint_as_float(l);
      }
      *(float4*)(sm + SAH + ar0 * 36 + aq0 * 4) = make_float4(h0[0], h0[1], h0[2], h0[3]);
      *(float4*)(sm + SAL + ar0 * 36 + aq0 * 4) = make_float4(l0[0], l0[1], l0[2], l0[3]);
      *(float4*)(sm + SAH + ar1 * 36 + aq1 * 4) = make_float4(h1[0], h1[1], h1[2], h1[3]);
      *(float4*)(sm + SAL + ar1 * 36 + aq1 * 4) = make_float4(l1[0], l1[1], l1[2], l1[3]);
    }
    // prefetch next feat chunk (overlaps with compute below)
    if (ch + 1 < 20) {
      pfA0 = *(const float4*)(g_feat + (size_t)(row0 + ar0) * KPAD + (ch + 1) * 32 + aq0 * 4);
      pfA1 = *(const float4*)(g_feat + (size_t)(row0 + ar1) * KPAD + (ch + 1) * 32 + aq1 * 4);
    }
    CP_WAIT0();
    __syncthreads();

#pragma unroll
    for (int k8 = 0; k8 < 4; k8++) {
      int kb = k8 * 8;
      unsigned ah[2][4], al[2][4];
#pragma unroll
      for (int mt = 0; mt < 2; mt++) {
        int r = mbase + mt * 16 + g;
        ah[mt][0] = __float_as_uint(sm[SAH + r * 36 + kb + tg]);
        al[mt][0] = __float_as_uint(sm[SAL + r * 36 + kb + tg]);
        ah[mt][1] = __float_as_uint(sm[SAH + (r + 8) * 36 + kb + tg]);
        al[mt][1] = __float_as_uint(sm[SAL + (r + 8) * 36 + kb + tg]);
        ah[mt][2] = __float_as_uint(sm[SAH + r * 36 + kb + tg + 4]);
        al[mt][2] = __float_as_uint(sm[SAL + r * 36 + kb + tg + 4]);
        ah[mt][3] = __float_as_uint(sm[SAH + (r + 8) * 36 + kb + tg + 4]);
        al[mt][3] = __float_as_uint(sm[SAL + (r + 8) * 36 + kb + tg + 4]);
      }
#pragma unroll
      for (int nt = 0; nt < 3; nt++) {
        int nb = nbase + nt * 8;
        unsigned b0h = __float_as_uint(sm[SBH + (kb + tg) * 100 + nb + g]);
        unsigned b1h = __float_as_uint(sm[SBH + (kb + tg + 4) * 100 + nb + g]);
        unsigned b0l = __float_as_uint(sm[SBL + (kb + tg) * 100 + nb + g]);
        unsigned b1l = __float_as_uint(sm[SBL + (kb + tg + 4) * 100 + nb + g]);
#pragma unroll
        for (int mt = 0; mt < 2; mt++) {
          mma_tf32(c[nt][mt], ah[mt], b0h, b1h);
          mma_tf32(c[nt][mt], ah[mt], b0l, b1l);
          mma_tf32(c[nt][mt], al[mt], b0h, b1h);
        }
      }
    }
  }

  // layer-1 writeback: bias + relu -> sH
  __syncthreads();
#pragma unroll
  for (int nt = 0; nt < 3; nt++) {
#pragma unroll
    for (int mt = 0; mt < 2; mt++) {
      int col = nbase + nt * 8 + 2 * tg;
      int r0 = mbase + mt * 16 + g;
      float bb0 = __ldg(b1 + col), bb1 = __ldg(b1 + col + 1);
      sm[SH + r0 * 100 + col] = fmaxf(c[nt][mt][0] + bb0, 0.f);
      sm[SH + r0 * 100 + col + 1] = fmaxf(c[nt][mt][1] + bb1, 0.f);
      sm[SH + (r0 + 8) * 100 + col] = fmaxf(c[nt][mt][2] + bb0, 0.f);
      sm[SH + (r0 + 8) * 100 + col + 1] = fmaxf(c[nt][mt][3] + bb1, 0.f);
#pragma unroll
      for (int f = 0; f < 4; f++) c[nt][mt][f] = 0.f;
    }
  }
  __syncthreads();

  // ================= layers 2 & 3: K = 96, 3 chunks of 32 =================
#pragma unroll 1
  for (int L = 0; L < 2; L++) {
    const float* Wh = L ? g_W3h : g_W2h;
    const float* Wl = L ? g_W3l : g_W2l;
    const float* bias = L ? b3 : b2;

#pragma unroll 1
    for (int ch = 0; ch < 3; ch++) {
      __syncthreads();
      cp16(smb + (SBH + wr0 * 100 + wq0 * 4) * 4, Wh + (size_t)(ch * 32 + wr0) * 96 + wq0 * 4);
      cp16(smb + (SBL + wr0 * 100 + wq0 * 4) * 4, Wl + (size_t)(ch * 32 + wr0) * 96 + wq0 * 4);
      cp16(smb + (SBH + wr1 * 100 + wq1 * 4) * 4, Wh + (size_t)(ch * 32 + wr1) * 96 + wq1 * 4);
      cp16(smb + (SBL + wr1 * 100 + wq1 * 4) * 4, Wl + (size_t)(ch * 32 + wr1) * 96 + wq1 * 4);
      cp16(smb + (SBH + wr2 * 100 + wq2 * 4) * 4, Wh + (size_t)(ch * 32 + wr2) * 96 + wq2 * 4);
      cp16(smb + (SBL + wr2 * 100 + wq2 * 4) * 4, Wl + (size_t)(ch * 32 + wr2) * 96 + wq2 * 4);
      CP_COMMIT();
      CP_WAIT0();
      __syncthreads();

#pragma unroll
      for (int k8 = 0; k8 < 4; k8++) {
        int kb = k8 * 8;
        int ka = ch * 32 + kb;
        unsigned ah[2][4], al[2][4];
#pragma unroll
        for (int mt = 0; mt < 2; mt++) {
          int r = mbase + mt * 16 + g;
          tf32_split(sm[SH + r * 100 + ka + tg], ah[mt][0], al[mt][0]);
          tf32_split(sm[SH + (r + 8) * 100 + ka + tg], ah[mt][1], al[mt][1]);
          tf32_split(sm[SH + r * 100 + ka + tg + 4], ah[mt][2], al[mt][2]);
          tf32_split(sm[SH + (r + 8) * 100 + ka + tg + 4], ah[mt][3], al[mt][3]);
        }
#pragma unroll
        for (int nt = 0; nt < 3; nt++) {
          int nb = nbase + nt * 8;
          unsigned b0h = __float_as_uint(sm[SBH + (kb + tg) * 100 + nb + g]);
          unsigned b1h = __float_as_uint(sm[SBH + (kb + tg + 4) * 100 + nb + g]);
          unsigned b0l = __float_as_uint(sm[SBL + (kb + tg) * 100 + nb + g]);
          unsigned b1l = __float_as_uint(sm[SBL + (kb + tg + 4) * 100 + nb + g]);
#pragma unroll
          for (int mt = 0; mt < 2; mt++) {
            mma_tf32(c[nt][mt], ah[mt], b0h, b1h);
            mma_tf32(c[nt][mt], ah[mt], b0l, b1l);
            mma_tf32(c[nt][mt], al[mt], b0h, b1h);
          }
        }
      }
    }

    // writeback (all reads of sH complete: C lives in regs)
    __syncthreads();
#pragma unroll
    for (int nt = 0; nt < 3; nt++) {
#pragma unroll
      for (int mt = 0; mt < 2; mt++) {
        int col = nbase + nt * 8 + 2 * tg;
        int r0 = mbase + mt * 16 + g;
        float bb0 = __ldg(bias + col), bb1 = __ldg(bias + col + 1);
        sm[SH + r0 * 100 + col] = fmaxf(c[nt][mt][0] + bb0, 0.f);
        sm[SH + r0 * 100 + col + 1] = fmaxf(c[nt][mt][1] + bb1, 0.f);
        sm[SH + (r0 + 8) * 100 + col] = fmaxf(c[nt][mt][2] + bb0, 0.f);
        sm[SH + (r0 + 8) * 100 + col + 1] = fmaxf(c[nt][mt][3] + bb1, 0.f);
#pragma unroll
        for (int f = 0; f < 4; f++) c[nt][mt][f] = 0.f;
      }
    }
    __syncthreads();
  }

  // ================= layer 4 (96 -> 4) + Gram-Schmidt =================
  if (tid < 64) {
    float o0 = 0.f, o1 = 0.f, o2 = 0.f, o3 = 0.f;
#pragma unroll 4
    for (int k = 0; k < 96; k++) {
      float hv = sm[SH + tid * 100 + k];
      float4 w = *(const float4*)(W4 + (size_t)k * 4);
      o0 = fmaf(hv, w.x, o0);
      o1 = fmaf(hv, w.y, o1);
      o2 = fmaf(hv, w.z, o2);
      o3 = fmaf(hv, w.w, o3);
    }
    float4 bv = *(const float4*)(b4);
    o0 += bv.x; o1 += bv.y; o2 += bv.z; o3 += bv.w;

    float n0 = 1.0f / sqrtf(o0 * o0 + o1 * o1);
    float e0x = o0 * n0, e0y = o1 * n0;
    float dt = e0x * o2 + e0y * o3;
    float u1x = o2 - dt * e0x, u1y = o3 - dt * e0y;
    float n1 = 1.0f / sqrtf(u1x * u1x + u1y * u1y);
    float e1x = u1x * n1, e1y = u1y * n1;
    float det = e0x * e1y - e1x * e0y;

    float* po = outp + (size_t)(row0 + tid) * 4;
    po[0] = e0x * det;
    po[1] = e1x;
    po[2] = e0y * det;
    po[3] = e1y;
  }
}

// ---------------------------------------------------------------------------
extern "C" void kernel_launch(void* const* d_in, const int* in_sizes, int n_in,
                              void* d_out, int out_size) {
  (void)in_sizes; (void)n_in; (void)out_size;
  const float* images = (const float*)d_in[0];
  const float* angles = (const float*)d_in[1];
  const float* W1 = (const float*)d_in[2];
  const float* b1 = (const float*)d_in[3];
  const float* W2 = (const float*)d_in[4];
  const float* b2 = (const float*)d_in[5];
  const float* W3 = (const float*)d_in[6];
  const float* b3 = (const float*)d_in[7];
  const float* W4 = (const float*)d_in[8];
  const float* b4 = (const float*)d_in[9];
  float* outp = (float*)d_out;

  cudaFuncSetAttribute(mlp_mma_kernel, cudaFuncAttributeMaxDynamicSharedMemorySize,
                       SM_FLOATS * 4);

  topk_feat_kernel<<<NIMG, 256>>>(images, angles);
  prep_weights<<<KPAD, 96>>>(W1, W2, W3);
  mlp_mma_kernel<<<NIMG / 64, 256, SM_FLOATS * 4>>>(b1, b2, b3, W4, b4, outp);
}

// round 12
// speedup vs baseline: 1.8310x; 1.0594x over previous
#include <cuda_runtime.h>
#include <math.h>

#define NIMG 32768
#define KPAD 640
#define DIN  620

// ---- device scratch (allocation-free) ----
__device__ __align__(16) float g_feat[(size_t)NIMG * KPAD];
// W stored FRAGMENT-MAJOR: [chunk][k8][nblk][lane][(b0,b1)]
__device__ __align__(16) float g_W1h[KPAD * 96];
__device__ __align__(16) float g_W1l[KPAD * 96];
__device__ __align__(16) float g_W2h[96 * 96];
__device__ __align__(16) float g_W2l[96 * 96];
__device__ __align__(16) float g_W3h[96 * 96];
__device__ __align__(16) float g_W3l[96 * 96];

// ---- tf32 helpers ----
__device__ __forceinline__ unsigned tf32_bits(float x) {
  unsigned r;
  asm("cvt.rna.tf32.f32 %0, %1;" : "=r"(r) : "f"(x));
  return r;
}
__device__ __forceinline__ void tf32_split(float x, unsigned& hi, unsigned& lo) {
  hi = tf32_bits(x);
  lo = tf32_bits(x - __uint_as_float(hi));
}

// D += A*B  (m16n8k8, tf32 inputs, f32 accum)
__device__ __forceinline__ void mma_tf32(float* c, const unsigned* a,
                                         unsigned b0, unsigned b1) {
  asm volatile(
      "mma.sync.aligned.m16n8k8.row.col.f32.tf32.tf32.f32 "
      "{%0,%1,%2,%3}, {%4,%5,%6,%7}, {%8,%9}, {%0,%1,%2,%3};"
      : "+f"(c[0]), "+f"(c[1]), "+f"(c[2]), "+f"(c[3])
      : "r"(a[0]), "r"(a[1]), "r"(a[2]), "r"(a[3]), "r"(b0), "r"(b1));
}

__device__ __forceinline__ unsigned smem_u32(const void* p) {
  unsigned a;
  asm("{ .reg .u64 t; cvta.to.shared.u64 t, %1; cvt.u32.u64 %0, t; }" : "=r"(a) : "l"(p));
  return a;
}
__device__ __forceinline__ void cp16(unsigned dst, const void* src) {
  asm volatile("cp.async.ca.shared.global [%0], [%1], 16;" :: "r"(dst), "l"(src));
}
#define CP_COMMIT() asm volatile("cp.async.commit_group;" ::: "memory")
#define CP_WAIT0()  asm volatile("cp.async.wait_group 0;" ::: "memory")

// ---------------------------------------------------------------------------
// Kernel A: per-image top-200 stable selection + feature build (R10 version:
// register-resident values, direct global writes)
// ---------------------------------------------------------------------------
__global__ __launch_bounds__(256) void topk_feat_kernel(
    const float* __restrict__ images, const float* __restrict__ angles) {
  __shared__ unsigned int hist[256];
  __shared__ unsigned int above[256];
  __shared__ unsigned int cursor[256];
  __shared__ unsigned long long bucketed[784];
  __shared__ unsigned int gsuf[33];
  __shared__ int sT;

  const int b = blockIdx.x;
  const int tid = threadIdx.x;
  const float* img = images + (size_t)b * 784;
  float* fo = g_feat + (size_t)b * KPAD;

  if (tid < 10) {
    float a = angles[(size_t)b * 10 + tid];
    float sn, cs;
    sincosf(a, &sn, &cs);
    fo[600 + 2 * tid] = cs;
    fo[601 + 2 * tid] = sn;
  } else if (tid < 30) {
    fo[620 + (tid - 10)] = 0.f;  // pad k = 620..639
  }

  hist[tid] = 0u;
  cursor[tid] = 0u;
  __syncthreads();

  float va[4];
  int qa[4];
  if (tid < 196) {
    float4 v4 = *(const float4*)(img + tid * 4);
    va[0] = v4.x; va[1] = v4.y; va[2] = v4.z; va[3] = v4.w;
#pragma unroll
    for (int j = 0; j < 4; j++) {
      qa[j] = min(255, (int)(va[j] * 256.0f));
      atomicAdd(&hist[qa[j]], 1u);
    }
  }
  __syncthreads();

  if (tid < 32) {
    unsigned int g = 0;
#pragma unroll
    for (int j = 0; j < 8; j++) g += hist[tid * 8 + j];
    unsigned int suf = g;
#pragma unroll
    for (int d = 1; d < 32; d <<= 1) {
      unsigned int o = __shfl_down_sync(0xffffffffu, suf, d);
      if (tid + d < 32) suf += o;
    }
    gsuf[tid] = suf;
    if (tid == 0) gsuf[32] = 0u;
  }
  __syncthreads();

  {
    int g = tid >> 3;
    unsigned int a = gsuf[g + 1];
    int hi8 = g * 8 + 7;
    for (int q = tid + 1; q <= hi8; q++) a += hist[q];
    above[tid] = a;
    if (a < 200u && a + hist[tid] >= 200u) sT = tid;
  }
  __syncthreads();
  const int T = sT;

  if (tid < 196) {
#pragma unroll
    for (int j = 0; j < 4; j++) {
      if (qa[j] >= T) {
        unsigned int pos = above[qa[j]] + atomicAdd(&cursor[qa[j]], 1u);
        bucketed[pos] = ((unsigned long long)__float_as_uint(va[j]) << 32) |
                        (unsigned int)(tid * 4 + j);
      }
    }
  }
  __syncthreads();

  const int ncand = (int)(above[T] + hist[T]);
  for (int s = tid; s < ncand; s += 256) {
    unsigned long long e = bucketed[s];
    unsigned int vb = (unsigned int)(e >> 32);
    unsigned int idx = (unsigned int)(e & 0xffffffffu);
    float v = __uint_as_float(vb);
    int q = min(255, (int)(v * 256.0f));
    int lo = (int)above[q];
    int hi = lo + (int)hist[q];
    int rank = lo;
    for (int m = lo; m < hi; m++) {
      if (m == s) continue;
      unsigned long long me = bucketed[m];
      unsigned int mvb = (unsigned int)(me >> 32);
      unsigned int midx = (unsigned int)(me & 0xffffffffu);
      if (mvb > vb || (mvb == vb && midx < idx)) rank++;
    }
    if (rank < 200) {
      int r = (int)idx / 28;
      int c = (int)idx - r * 28;
      float cx = (c < 14) ? (float)(c - 14) : (float)(c - 13);
      float cy = (r < 14) ? (float)(14 - r) : (float)(13 - r);
      float vv = v;
      if (vv < 0.1f) { vv = 0.f; cx = 0.f; cy = 0.f; }
      fo[rank] = vv;
      fo[200 + 2 * rank] = cx;
      fo[201 + 2 * rank] = cy;
    }
  }
}

// ---------------------------------------------------------------------------
// Weight prep: tf32 hi/lo split, FRAGMENT-MAJOR layout:
// addr = ch*3072 + (k8*12 + nblk)*64 + lane*2 + hic,  lane = g*4 + tg
// where (within chunk) k8=kk/8, tg=kk%4, hic=(kk%8)/4, g=n%8, nblk=n/8
// ---------------------------------------------------------------------------
__global__ void prep_weights(const float* __restrict__ W1,
                             const float* __restrict__ W2,
                             const float* __restrict__ W3) {
  int k = blockIdx.x;   // 0..639
  int n = threadIdx.x;  // 0..95
  int ch = k >> 5;
  int kk = k & 31;
  int k8 = kk >> 3;
  int c8 = kk & 7;
  int tg = c8 & 3;
  int hic = c8 >> 2;
  int g = n & 7;
  int nblk = n >> 3;
  size_t addr = (size_t)ch * 3072 + (size_t)(k8 * 12 + nblk) * 64 + (g * 4 + tg) * 2 + hic;
  {
    float v = (k < DIN) ? W1[(size_t)k * 96 + n] : 0.f;
    unsigned h, l;
    tf32_split(v, h, l);
    g_W1h[addr] = __uint_as_float(h);
    g_W1l[addr] = __uint_as_float(l);
  }
  if (k < 96) {
    unsigned h, l;
    tf32_split(W2[(size_t)k * 96 + n], h, l);
    g_W2h[addr] = __uint_as_float(h);
    g_W2l[addr] = __uint_as_float(l);
    tf32_split(W3[(size_t)k * 96 + n], h, l);
    g_W3h[addr] = __uint_as_float(h);
    g_W3l[addr] = __uint_as_float(l);
  }
}

// ---------------------------------------------------------------------------
// Kernel B: 3xTF32 mma.sync MLP + Gram-Schmidt epilogue
// Fragment-major A (layer 1) and B (all layers) smem: inner loop is
// 4 LDS.128 + 6 LDS.64 + 18 mma per k8.
// ---------------------------------------------------------------------------
#define SAH 0        // A hi fragment slab (2064 + pad)
#define SAL 2080
#define SBH 4160     // W hi fragment slab [3072]
#define SBL 7232
#define SH  10304    // activations [64][100]
#define SM_FLOATS 16704  // 66816 bytes

__global__ __launch_bounds__(256) void mlp_mma_kernel(
    const float* __restrict__ b1, const float* __restrict__ b2,
    const float* __restrict__ b3, const float* __restrict__ W4,
    const float* __restrict__ b4, float* __restrict__ outp) {
  extern __shared__ float sm[];
  const unsigned smb = smem_u32(sm);
  const int tid = threadIdx.x;
  const int warp = tid >> 5;
  const int lane = tid & 31;
  const int g = lane >> 2;
  const int tg = lane & 3;
  const int nbase = (warp & 3) * 24;
  const int mbase = (warp >> 2) * 32;
  const int row0 = blockIdx.x * 64;

  // A-writer coordinates: thread owns rows ar*, k-cols aq*4..aq*4+3
  const int ar0 = tid >> 3, aq0 = tid & 7;
  const int ar1 = (tid + 256) >> 3, aq1 = (tid + 256) & 7;
  // fragment store bases: addr(j) = segbase + j*4
  const int k8a0 = aq0 >> 1, hic0 = aq0 & 1;
  const int segbase0 = (k8a0 * 4 + (ar0 >> 4)) * 128 + k8a0 * 4 +
                       ((ar0 & 7) * 16) + hic0 * 2 + ((ar0 & 15) >> 3);
  const int k8a1 = aq1 >> 1, hic1 = aq1 & 1;
  const int segbase1 = (k8a1 * 4 + (ar1 >> 4)) * 128 + k8a1 * 4 +
                       ((ar1 & 7) * 16) + hic1 * 2 + ((ar1 & 15) >> 3);

  float c[3][2][4];
#pragma unroll
  for (int nt = 0; nt < 3; nt++)
#pragma unroll
    for (int mt = 0; mt < 2; mt++)
#pragma unroll
      for (int f = 0; f < 4; f++) c[nt][mt][f] = 0.f;

  // prefetch feat chunk 0
  float4 pfA0 = *(const float4*)(g_feat + (size_t)(row0 + ar0) * KPAD + aq0 * 4);
  float4 pfA1 = *(const float4*)(g_feat + (size_t)(row0 + ar1) * KPAD + aq1 * 4);

  // ================= layer 1: K = 640, 20 chunks of 32 =================
  for (int ch = 0; ch < 20; ch++) {
    __syncthreads();  // stage consumers done
    // W fragment slabs via cp.async (contiguous)
#pragma unroll
    for (int i = 0; i < 3; i++) {
      int idx = tid + i * 256;  // float4 index, 0..767
      cp16(smb + (SBH + idx * 4) * 4, g_W1h + (size_t)ch * 3072 + idx * 4);
      cp16(smb + (SBL + idx * 4) * 4, g_W1l + (size_t)ch * 3072 + idx * 4);
    }
    CP_COMMIT();

    // A: split prefetched regs -> fragment-major SAH/SAL
    {
      float v0[4] = {pfA0.x, pfA0.y, pfA0.z, pfA0.w};
      float v1[4] = {pfA1.x, pfA1.y, pfA1.z, pfA1.w};
#pragma unroll
      for (int j = 0; j < 4; j++) {
        unsigned h, l;
        tf32_split(v0[j], h, l);
        sm[SAH + segbase0 + j * 4] = __uint_as_float(h);
        sm[SAL + segbase0 + j * 4] = __uint_as_float(l);
        tf32_split(v1[j], h, l);
        sm[SAH + segbase1 + j * 4] = __uint_as_float(h);
        sm[SAL + segbase1 + j * 4] = __uint_as_float(l);
      }
    }
    // prefetch next feat chunk (overlaps with compute below)
    if (ch + 1 < 20) {
      pfA0 = *(const float4*)(g_feat + (size_t)(row0 + ar0) * KPAD + (ch + 1) * 32 + aq0 * 4);
      pfA1 = *(const float4*)(g_feat + (size_t)(row0 + ar1) * KPAD + (ch + 1) * 32 + aq1 * 4);
    }
    CP_WAIT0();
    __syncthreads();

#pragma unroll
    for (int k8 = 0; k8 < 4; k8++) {
      float4 ahf[2], alf[2];
#pragma unroll
      for (int mt = 0; mt < 2; mt++) {
        int mb = (warp >> 2) * 2 + mt;
        int off = (k8 * 4 + mb) * 128 + k8 * 4 + lane * 4;
        ahf[mt] = *(const float4*)(sm + SAH + off);
        alf[mt] = *(const float4*)(sm + SAL + off);
      }
#pragma unroll
      for (int nt = 0; nt < 3; nt++) {
        int nblk = (warp & 3) * 3 + nt;
        int boff = (k8 * 12 + nblk) * 64 + lane * 2;
        float2 bh = *(const float2*)(sm + SBH + boff);
        float2 bl = *(const float2*)(sm + SBL + boff);
        unsigned b0h = __float_as_uint(bh.x), b1h = __float_as_uint(bh.y);
        unsigned b0l = __float_as_uint(bl.x), b1l = __float_as_uint(bl.y);
#pragma unroll
        for (int mt = 0; mt < 2; mt++) {
          mma_tf32(c[nt][mt], (const unsigned*)&ahf[mt], b0h, b1h);
          mma_tf32(c[nt][mt], (const unsigned*)&ahf[mt], b0l, b1l);
          mma_tf32(c[nt][mt], (const unsigned*)&alf[mt], b0h, b1h);
        }
      }
    }
  }

  // layer-1 writeback: bias + relu -> sH
  __syncthreads();
#pragma unroll
  for (int nt = 0; nt < 3; nt++) {
#pragma unroll
    for (int mt = 0; mt < 2; mt++) {
      int col = nbase + nt * 8 + 2 * tg;
      int r0 = mbase + mt * 16 + g;
      float bb0 = __ldg(b1 + col), bb1 = __ldg(b1 + col + 1);
      sm[SH + r0 * 100 + col] = fmaxf(c[nt][mt][0] + bb0, 0.f);
      sm[SH + r0 * 100 + col + 1] = fmaxf(c[nt][mt][1] + bb1, 0.f);
      sm[SH + (r0 + 8) * 100 + col] = fmaxf(c[nt][mt][2] + bb0, 0.f);
      sm[SH + (r0 + 8) * 100 + col + 1] = fmaxf(c[nt][mt][3] + bb1, 0.f);
#pragma unroll
      for (int f = 0; f < 4; f++) c[nt][mt][f] = 0.f;
    }
  }
  __syncthreads();

  // ================= layers 2 & 3: K = 96, 3 chunks of 32 =================
#pragma unroll 1
  for (int L = 0; L < 2; L++) {
    const float* Wh = L ? g_W3h : g_W2h;
    const float* Wl = L ? g_W3l : g_W2l;
    const float* bias = L ? b3 : b2;

#pragma unroll 1
    for (int ch = 0; ch < 3; ch++) {
      __syncthreads();
#pragma unroll
      for (int i = 0; i < 3; i++) {
        int idx = tid + i * 256;
        cp16(smb + (SBH + idx * 4) * 4, Wh + (size_t)ch * 3072 + idx * 4);
        cp16(smb + (SBL + idx * 4) * 4, Wl + (size_t)ch * 3072 + idx * 4);
      }
      CP_COMMIT();
      CP_WAIT0();
      __syncthreads();

#pragma unroll
      for (int k8 = 0; k8 < 4; k8++) {
        int ka = ch * 32 + k8 * 8;
        unsigned ah[2][4], al[2][4];
#pragma unroll
        for (int mt = 0; mt < 2; mt++) {
          int r = mbase + mt * 16 + g;
          tf32_split(sm[SH + r * 100 + ka + tg], ah[mt][0], al[mt][0]);
          tf32_split(sm[SH + (r + 8) * 100 + ka + tg], ah[mt][1], al[mt][1]);
          tf32_split(sm[SH + r * 100 + ka + tg + 4], ah[mt][2], al[mt][2]);
          tf32_split(sm[SH + (r + 8) * 100 + ka + tg + 4], ah[mt][3], al[mt][3]);
        }
#pragma unroll
        for (int nt = 0; nt < 3; nt++) {
          int nblk = (warp & 3) * 3 + nt;
          int boff = (k8 * 12 + nblk) * 64 + lane * 2;
          float2 bh = *(const float2*)(sm + SBH + boff);
          float2 bl = *(const float2*)(sm + SBL + boff);
          unsigned b0h = __float_as_uint(bh.x), b1h = __float_as_uint(bh.y);
          unsigned b0l = __float_as_uint(bl.x), b1l = __float_as_uint(bl.y);
#pragma unroll
          for (int mt = 0; mt < 2; mt++) {
            mma_tf32(c[nt][mt], ah[mt], b0h, b1h);
            mma_tf32(c[nt][mt], ah[mt], b0l, b1l);
            mma_tf32(c[nt][mt], al[mt], b0h, b1h);
          }
        }
      }
    }

    // writeback (all reads of sH complete: C lives in regs)
    __syncthreads();
#pragma unroll
    for (int nt = 0; nt < 3; nt++) {
#pragma unroll
      for (int mt = 0; mt < 2; mt++) {
        int col = nbase + nt * 8 + 2 * tg;
        int r0 = mbase + mt * 16 + g;
        float bb0 = __ldg(bias + col), bb1 = __ldg(bias + col + 1);
        sm[SH + r0 * 100 + col] = fmaxf(c[nt][mt][0] + bb0, 0.f);
        sm[SH + r0 * 100 + col + 1] = fmaxf(c[nt][mt][1] + bb1, 0.f);
        sm[SH + (r0 + 8) * 100 + col] = fmaxf(c[nt][mt][2] + bb0, 0.f);
        sm[SH + (r0 + 8) * 100 + col + 1] = fmaxf(c[nt][mt][3] + bb1, 0.f);
#pragma unroll
        for (int f = 0; f < 4; f++) c[nt][mt][f] = 0.f;
      }
    }
    __syncthreads();
  }

  // ================= layer 4 (96 -> 4) + Gram-Schmidt =================
  if (tid < 64) {
    float o0 = 0.f, o1 = 0.f, o2 = 0.f, o3 = 0.f;
#pragma unroll 4
    for (int k = 0; k < 96; k++) {
      float hv = sm[SH + tid * 100 + k];
      float4 w = *(const float4*)(W4 + (size_t)k * 4);
      o0 = fmaf(hv, w.x, o0);
      o1 = fmaf(hv, w.y, o1);
      o2 = fmaf(hv, w.z, o2);
      o3 = fmaf(hv, w.w, o3);
    }
    float4 bv = *(const float4*)(b4);
    o0 += bv.x; o1 += bv.y; o2 += bv.z; o3 += bv.w;

    float n0 = 1.0f / sqrtf(o0 * o0 + o1 * o1);
    float e0x = o0 * n0, e0y = o1 * n0;
    float dt = e0x * o2 + e0y * o3;
    float u1x = o2 - dt * e0x, u1y = o3 - dt * e0y;
    float n1 = 1.0f / sqrtf(u1x * u1x + u1y * u1y);
    float e1x = u1x * n1, e1y = u1y * n1;
    float det = e0x * e1y - e1x * e0y;

    float* po = outp + (size_t)(row0 + tid) * 4;
    po[0] = e0x * det;
    po[1] = e1x;
    po[2] = e0y * det;
    po[3] = e1y;
  }
}

// ---------------------------------------------------------------------------
extern "C" void kernel_launch(void* const* d_in, const int* in_sizes, int n_in,
                              void* d_out, int out_size) {
  (void)in_sizes; (void)n_in; (void)out_size;
  const float* images = (const float*)d_in[0];
  const float* angles = (const float*)d_in[1];
  const float* W1 = (const float*)d_in[2];
  const float* b1 = (const float*)d_in[3];
  const float* W2 = (const float*)d_in[4];
  const float* b2 = (const float*)d_in[5];
  const float* W3 = (const float*)d_in[6];
  const float* b3 = (const float*)d_in[7];
  const float* W4 = (const float*)d_in[8];
  const float* b4 = (const float*)d_in[9];
  float* outp = (float*)d_out;

  cudaFuncSetAttribute(mlp_mma_kernel, cudaFuncAttributeMaxDynamicSharedMemorySize,
                       SM_FLOATS * 4);

  topk_feat_kernel<<<NIMG, 256>>>(images, angles);
  prep_weights<<<KPAD, 96>>>(W1, W2, W3);
  mlp_mma_kernel<<<NIMG / 64, 256, SM_FLOATS * 4>>>(b1, b2, b3, W4, b4, outp);
}

// round 13
// speedup vs baseline: 1.8586x; 1.0151x over previous
#include <cuda_runtime.h>
#include <math.h>

#define NIMG 32768
#define KPAD 640
#define DIN  620

// ---- device scratch (allocation-free) ----
__device__ __align__(16) float g_feat[(size_t)NIMG * KPAD];
// W stored FRAGMENT-MAJOR: [chunk][k8][nblk][lane][(b0,b1)]
__device__ __align__(16) float g_W1h[KPAD * 96];
__device__ __align__(16) float g_W1l[KPAD * 96];
__device__ __align__(16) float g_W2h[96 * 96];
__device__ __align__(16) float g_W2l[96 * 96];
__device__ __align__(16) float g_W3h[96 * 96];
__device__ __align__(16) float g_W3l[96 * 96];

// ---- tf32 helpers ----
__device__ __forceinline__ unsigned tf32_bits(float x) {
  unsigned r;
  asm("cvt.rna.tf32.f32 %0, %1;" : "=r"(r) : "f"(x));
  return r;
}
__device__ __forceinline__ void tf32_split(float x, unsigned& hi, unsigned& lo) {
  hi = tf32_bits(x);
  lo = tf32_bits(x - __uint_as_float(hi));
}

// D += A*B  (m16n8k8, tf32 inputs, f32 accum)
__device__ __forceinline__ void mma_tf32(float* c, const unsigned* a,
                                         unsigned b0, unsigned b1) {
  asm volatile(
      "mma.sync.aligned.m16n8k8.row.col.f32.tf32.tf32.f32 "
      "{%0,%1,%2,%3}, {%4,%5,%6,%7}, {%8,%9}, {%0,%1,%2,%3};"
      : "+f"(c[0]), "+f"(c[1]), "+f"(c[2]), "+f"(c[3])
      : "r"(a[0]), "r"(a[1]), "r"(a[2]), "r"(a[3]), "r"(b0), "r"(b1));
}

__device__ __forceinline__ unsigned smem_u32(const void* p) {
  unsigned a;
  asm("{ .reg .u64 t; cvta.to.shared.u64 t, %1; cvt.u32.u64 %0, t; }" : "=r"(a) : "l"(p));
  return a;
}
__device__ __forceinline__ void cp16(unsigned dst, const void* src) {
  asm volatile("cp.async.ca.shared.global [%0], [%1], 16;" :: "r"(dst), "l"(src));
}
#define CP_COMMIT() asm volatile("cp.async.commit_group;" ::: "memory")
#define CP_WAIT0()  asm volatile("cp.async.wait_group 0;" ::: "memory")
#define CP_WAIT1()  asm volatile("cp.async.wait_group 1;" ::: "memory")

// ---------------------------------------------------------------------------
// Kernel A: per-image top-200 stable selection + feature build.
// Register-resident values; shfl-based block suffix scan for per-bin counts.
// ---------------------------------------------------------------------------
__global__ __launch_bounds__(256) void topk_feat_kernel(
    const float* __restrict__ images, const float* __restrict__ angles) {
  __shared__ unsigned int hist[256];
  __shared__ unsigned int above[256];
  __shared__ unsigned int cursor[256];
  __shared__ unsigned long long bucketed[784];
  __shared__ unsigned int wtot[8];
  __shared__ unsigned int wsuf[8];
  __shared__ int sT;

  const int b = blockIdx.x;
  const int tid = threadIdx.x;
  const float* img = images + (size_t)b * 784;
  float* fo = g_feat + (size_t)b * KPAD;

  if (tid < 10) {
    float a = angles[(size_t)b * 10 + tid];
    float sn, cs;
    sincosf(a, &sn, &cs);
    fo[600 + 2 * tid] = cs;
    fo[601 + 2 * tid] = sn;
  } else if (tid < 30) {
    fo[620 + (tid - 10)] = 0.f;  // pad k = 620..639
  }

  hist[tid] = 0u;
  cursor[tid] = 0u;
  __syncthreads();

  // Pass 1: 196 threads load float4, histogram; values stay in registers.
  // images are uniform [0,1): (int)(v*256) is always in [0,255].
  float va[4];
  int qa[4];
  if (tid < 196) {
    float4 v4 = *(const float4*)(img + tid * 4);
    va[0] = v4.x; va[1] = v4.y; va[2] = v4.z; va[3] = v4.w;
#pragma unroll
    for (int j = 0; j < 4; j++) {
      qa[j] = (int)(va[j] * 256.0f);
      atomicAdd(&hist[qa[j]], 1u);
    }
  }
  __syncthreads();

  // Pass 2: block suffix scan -> above[q] = count of elements in bins > q
  unsigned h = hist[tid];
  unsigned s = h;
#pragma unroll
  for (int d = 1; d < 32; d <<= 1) {
    unsigned o = __shfl_down_sync(0xffffffffu, s, d);
    if ((tid & 31) + d < 32) s += o;
  }
  if ((tid & 31) == 0) wtot[tid >> 5] = s;
  __syncthreads();
  if (tid < 8) {
    unsigned t = 0;
    for (int j = tid + 1; j < 8; j++) t += wtot[j];
    wsuf[tid] = t;
  }
  __syncthreads();
  {
    unsigned a = (s - h) + wsuf[tid >> 5];
    above[tid] = a;
    if (a < 200u && a + h >= 200u) sT = tid;
  }
  __syncthreads();
  const int T = sT;

  // Pass 3: scatter candidates (q >= T) into bucket-grouped slots
  if (tid < 196) {
#pragma unroll
    for (int j = 0; j < 4; j++) {
      if (qa[j] >= T) {
        unsigned int pos = above[qa[j]] + atomicAdd(&cursor[qa[j]], 1u);
        bucketed[pos] = ((unsigned long long)__float_as_uint(va[j]) << 32) |
                        (unsigned int)(tid * 4 + j);
      }
    }
  }
  __syncthreads();

  // Pass 4: exact stable rank; write features at rank
  const int ncand = (int)(above[T] + hist[T]);
  for (int sI = tid; sI < ncand; sI += 256) {
    unsigned long long e = bucketed[sI];
    unsigned int vb = (unsigned int)(e >> 32);
    unsigned int idx = (unsigned int)(e & 0xffffffffu);
    float v = __uint_as_float(vb);
    int q = (int)(v * 256.0f);
    int lo = (int)above[q];
    int hi = lo + (int)hist[q];
    int rank = lo;
    for (int m = lo; m < hi; m++) {
      if (m == sI) continue;
      unsigned long long me = bucketed[m];
      unsigned int mvb = (unsigned int)(me >> 32);
      unsigned int midx = (unsigned int)(me & 0xffffffffu);
      if (mvb > vb || (mvb == vb && midx < idx)) rank++;
    }
    if (rank < 200) {
      int r = (int)idx / 28;
      int c = (int)idx - r * 28;
      float cx = (c < 14) ? (float)(c - 14) : (float)(c - 13);
      float cy = (r < 14) ? (float)(14 - r) : (float)(13 - r);
      float vv = v;
      if (vv < 0.1f) { vv = 0.f; cx = 0.f; cy = 0.f; }
      fo[rank] = vv;
      fo[200 + 2 * rank] = cx;
      fo[201 + 2 * rank] = cy;
    }
  }
}

// ---------------------------------------------------------------------------
// Weight prep: tf32 hi/lo split, fragment-major layout
// ---------------------------------------------------------------------------
__global__ void prep_weights(const float* __restrict__ W1,
                             const float* __restrict__ W2,
                             const float* __restrict__ W3) {
  int k = blockIdx.x;   // 0..639
  int n = threadIdx.x;  // 0..95
  int ch = k >> 5;
  int kk = k & 31;
  int k8 = kk >> 3;
  int c8 = kk & 7;
  int tg = c8 & 3;
  int hic = c8 >> 2;
  int g = n & 7;
  int nblk = n >> 3;
  size_t addr = (size_t)ch * 3072 + (size_t)(k8 * 12 + nblk) * 64 + (g * 4 + tg) * 2 + hic;
  {
    float v = (k < DIN) ? W1[(size_t)k * 96 + n] : 0.f;
    unsigned h, l;
    tf32_split(v, h, l);
    g_W1h[addr] = __uint_as_float(h);
    g_W1l[addr] = __uint_as_float(l);
  }
  if (k < 96) {
    unsigned h, l;
    tf32_split(W2[(size_t)k * 96 + n], h, l);
    g_W2h[addr] = __uint_as_float(h);
    g_W2l[addr] = __uint_as_float(l);
    tf32_split(W3[(size_t)k * 96 + n], h, l);
    g_W3h[addr] = __uint_as_float(h);
    g_W3l[addr] = __uint_as_float(l);
  }
}

// ---------------------------------------------------------------------------
// Kernel B: 3xTF32 mma.sync MLP, ping-pong double-buffered W slabs
// ---------------------------------------------------------------------------
#define SBH0 0
#define SBL0 3072
#define SBH1 6144
#define SBL1 9216
#define SAH  12288   // A hi fragment slab (2080)
#define SAL  14368
#define SH   16448   // activations [64][100]
#define SM_FLOATS 22848  // 91392 bytes

__device__ __forceinline__ void issue_W(unsigned smb, int sbh, int sbl,
                                        const float* __restrict__ Wh,
                                        const float* __restrict__ Wl,
                                        int ch, int tid) {
#pragma unroll
  for (int i = 0; i < 3; i++) {
    int idx = tid + i * 256;  // float4 index 0..767
    cp16(smb + (sbh + idx * 4) * 4, Wh + (size_t)ch * 3072 + idx * 4);
    cp16(smb + (sbl + idx * 4) * 4, Wl + (size_t)ch * 3072 + idx * 4);
  }
}

__global__ __launch_bounds__(256) void mlp_mma_kernel(
    const float* __restrict__ b1, const float* __restrict__ b2,
    const float* __restrict__ b3, const float* __restrict__ W4,
    const float* __restrict__ b4, float* __restrict__ outp) {
  extern __shared__ float sm[];
  const unsigned smb = smem_u32(sm);
  const int tid = threadIdx.x;
  const int warp = tid >> 5;
  const int lane = tid & 31;
  const int g = lane >> 2;
  const int tg = lane & 3;
  const int nbase = (warp & 3) * 24;
  const int mbase = (warp >> 2) * 32;
  const int row0 = blockIdx.x * 64;

  const int ar0 = tid >> 3, aq0 = tid & 7;
  const int ar1 = (tid + 256) >> 3, aq1 = (tid + 256) & 7;
  const int k8a0 = aq0 >> 1, hic0 = aq0 & 1;
  const int segbase0 = (k8a0 * 4 + (ar0 >> 4)) * 128 + k8a0 * 4 +
                       ((ar0 & 7) * 16) + hic0 * 2 + ((ar0 & 15) >> 3);
  const int k8a1 = aq1 >> 1, hic1 = aq1 & 1;
  const int segbase1 = (k8a1 * 4 + (ar1 >> 4)) * 128 + k8a1 * 4 +
                       ((ar1 & 7) * 16) + hic1 * 2 + ((ar1 & 15) >> 3);

  float c[3][2][4];
#pragma unroll
  for (int nt = 0; nt < 3; nt++)
#pragma unroll
    for (int mt = 0; mt < 2; mt++)
#pragma unroll
      for (int f = 0; f < 4; f++) c[nt][mt][f] = 0.f;

  // prefetch feat chunk 0 + issue W chunk 0
  float4 pfA0 = *(const float4*)(g_feat + (size_t)(row0 + ar0) * KPAD + aq0 * 4);
  float4 pfA1 = *(const float4*)(g_feat + (size_t)(row0 + ar1) * KPAD + aq1 * 4);
  issue_W(smb, SBH0, SBL0, g_W1h, g_W1l, 0, tid);
  CP_COMMIT();

  // ================= layer 1: K = 640, 20 chunks of 32 =================
  for (int ch = 0; ch < 20; ch++) {
    const int sbh = (ch & 1) ? SBH1 : SBH0;
    const int sbl = (ch & 1) ? SBL1 : SBL0;
    const int nsbh = (ch & 1) ? SBH0 : SBH1;
    const int nsbl = (ch & 1) ? SBL0 : SBL1;
    __syncthreads();  // previous compute done reading next buffer & SA
    if (ch + 1 < 20) {
      issue_W(smb, nsbh, nsbl, g_W1h, g_W1l, ch + 1, tid);
      CP_COMMIT();
    }
    // A: split prefetched regs -> fragment-major SAH/SAL
    {
      float v0[4] = {pfA0.x, pfA0.y, pfA0.z, pfA0.w};
      float v1[4] = {pfA1.x, pfA1.y, pfA1.z, pfA1.w};
#pragma unroll
      for (int j = 0; j < 4; j++) {
        unsigned h, l;
        tf32_split(v0[j], h, l);
        sm[SAH + segbase0 + j * 4] = __uint_as_float(h);
        sm[SAL + segbase0 + j * 4] = __uint_as_float(l);
        tf32_split(v1[j], h, l);
        sm[SAH + segbase1 + j * 4] = __uint_as_float(h);
        sm[SAL + segbase1 + j * 4] = __uint_as_float(l);
      }
    }
    if (ch + 1 < 20) {
      pfA0 = *(const float4*)(g_feat + (size_t)(row0 + ar0) * KPAD + (ch + 1) * 32 + aq0 * 4);
      pfA1 = *(const float4*)(g_feat + (size_t)(row0 + ar1) * KPAD + (ch + 1) * 32 + aq1 * 4);
      CP_WAIT1();   // current chunk's W landed; next chunk's still in flight
    } else {
      CP_WAIT0();
    }
    __syncthreads();

#pragma unroll
    for (int k8 = 0; k8 < 4; k8++) {
      float4 ahf[2], alf[2];
#pragma unroll
      for (int mt = 0; mt < 2; mt++) {
        int mb = (warp >> 2) * 2 + mt;
        int off = (k8 * 4 + mb) * 128 + k8 * 4 + lane * 4;
        ahf[mt] = *(const float4*)(sm + SAH + off);
        alf[mt] = *(const float4*)(sm + SAL + off);
      }
#pragma unroll
      for (int nt = 0; nt < 3; nt++) {
        int nblk = (warp & 3) * 3 + nt;
        int boff = (k8 * 12 + nblk) * 64 + lane * 2;
        float2 bh = *(const float2*)(sm + sbh + boff);
        float2 bl = *(const float2*)(sm + sbl + boff);
        unsigned b0h = __float_as_uint(bh.x), b1h = __float_as_uint(bh.y);
        unsigned b0l = __float_as_uint(bl.x), b1l = __float_as_uint(bl.y);
#pragma unroll
        for (int mt = 0; mt < 2; mt++) {
          mma_tf32(c[nt][mt], (const unsigned*)&ahf[mt], b0h, b1h);
          mma_tf32(c[nt][mt], (const unsigned*)&ahf[mt], b0l, b1l);
          mma_tf32(c[nt][mt], (const unsigned*)&alf[mt], b0h, b1h);
        }
      }
    }
  }

  // layer-1 writeback: bias + relu -> sH
  __syncthreads();
#pragma unroll
  for (int nt = 0; nt < 3; nt++) {
#pragma unroll
    for (int mt = 0; mt < 2; mt++) {
      int col = nbase + nt * 8 + 2 * tg;
      int r0 = mbase + mt * 16 + g;
      float bb0 = __ldg(b1 + col), bb1 = __ldg(b1 + col + 1);
      sm[SH + r0 * 100 + col] = fmaxf(c[nt][mt][0] + bb0, 0.f);
      sm[SH + r0 * 100 + col + 1] = fmaxf(c[nt][mt][1] + bb1, 0.f);
      sm[SH + (r0 + 8) * 100 + col] = fmaxf(c[nt][mt][2] + bb0, 0.f);
      sm[SH + (r0 + 8) * 100 + col + 1] = fmaxf(c[nt][mt][3] + bb1, 0.f);
#pragma unroll
      for (int f = 0; f < 4; f++) c[nt][mt][f] = 0.f;
    }
  }
  __syncthreads();

  // ================= layers 2 & 3: K = 96, 3 chunks of 32 =================
#pragma unroll 1
  for (int L = 0; L < 2; L++) {
    const float* Wh = L ? g_W3h : g_W2h;
    const float* Wl = L ? g_W3l : g_W2l;
    const float* bias = L ? b3 : b2;

    issue_W(smb, SBH0, SBL0, Wh, Wl, 0, tid);
    CP_COMMIT();

#pragma unroll 1
    for (int ch = 0; ch < 3; ch++) {
      const int sbh = (ch & 1) ? SBH1 : SBH0;
      const int sbl = (ch & 1) ? SBL1 : SBL0;
      const int nsbh = (ch & 1) ? SBH0 : SBH1;
      const int nsbl = (ch & 1) ? SBL0 : SBL1;
      __syncthreads();
      if (ch + 1 < 3) {
        issue_W(smb, nsbh, nsbl, Wh, Wl, ch + 1, tid);
        CP_COMMIT();
        CP_WAIT1();
      } else {
        CP_WAIT0();
      }
      __syncthreads();

#pragma unroll
      for (int k8 = 0; k8 < 4; k8++) {
        int ka = ch * 32 + k8 * 8;
        unsigned ah[2][4], al[2][4];
#pragma unroll
        for (int mt = 0; mt < 2; mt++) {
          int r = mbase + mt * 16 + g;
          tf32_split(sm[SH + r * 100 + ka + tg], ah[mt][0], al[mt][0]);
          tf32_split(sm[SH + (r + 8) * 100 + ka + tg], ah[mt][1], al[mt][1]);
          tf32_split(sm[SH + r * 100 + ka + tg + 4], ah[mt][2], al[mt][2]);
          tf32_split(sm[SH + (r + 8) * 100 + ka + tg + 4], ah[mt][3], al[mt][3]);
        }
#pragma unroll
        for (int nt = 0; nt < 3; nt++) {
          int nblk = (warp & 3) * 3 + nt;
          int boff = (k8 * 12 + nblk) * 64 + lane * 2;
          float2 bh = *(const float2*)(sm + sbh + boff);
          float2 bl = *(const float2*)(sm + sbl + boff);
          unsigned b0h = __float_as_uint(bh.x), b1h = __float_as_uint(bh.y);
          unsigned b0l = __float_as_uint(bl.x), b1l = __float_as_uint(bl.y);
#pragma unroll
          for (int mt = 0; mt < 2; mt++) {
            mma_tf32(c[nt][mt], ah[mt], b0h, b1h);
            mma_tf32(c[nt][mt], ah[mt], b0l, b1l);
            mma_tf32(c[nt][mt], al[mt], b0h, b1h);
          }
        }
      }
    }

    // writeback (all reads of sH complete: C lives in regs)
    __syncthreads();
#pragma unroll
    for (int nt = 0; nt < 3; nt++) {
#pragma unroll
      for (int mt = 0; mt < 2; mt++) {
        int col = nbase + nt * 8 + 2 * tg;
        int r0 = mbase + mt * 16 + g;
        float bb0 = __ldg(bias + col), bb1 = __ldg(bias + col + 1);
        sm[SH + r0 * 100 + col] = fmaxf(c[nt][mt][0] + bb0, 0.f);
        sm[SH + r0 * 100 + col + 1] = fmaxf(c[nt][mt][1] + bb1, 0.f);
        sm[SH + (r0 + 8) * 100 + col] = fmaxf(c[nt][mt][2] + bb0, 0.f);
        sm[SH + (r0 + 8) * 100 + col + 1] = fmaxf(c[nt][mt][3] + bb1, 0.f);
#pragma unroll
        for (int f = 0; f < 4; f++) c[nt][mt][f] = 0.f;
      }
    }
    __syncthreads();
  }

  // ================= layer 4 (96 -> 4) + Gram-Schmidt =================
  if (tid < 64) {
    float o0 = 0.f, o1 = 0.f, o2 = 0.f, o3 = 0.f;
#pragma unroll 4
    for (int k = 0; k < 96; k++) {
      float hv = sm[SH + tid * 100 + k];
      float4 w = *(const float4*)(W4 + (size_t)k * 4);
      o0 = fmaf(hv, w.x, o0);
      o1 = fmaf(hv, w.y, o1);
      o2 = fmaf(hv, w.z, o2);
      o3 = fmaf(hv, w.w, o3);
    }
    float4 bv = *(const float4*)(b4);
    o0 += bv.x; o1 += bv.y; o2 += bv.z; o3 += bv.w;

    float n0 = 1.0f / sqrtf(o0 * o0 + o1 * o1);
    float e0x = o0 * n0, e0y = o1 * n0;
    float dt = e0x * o2 + e0y * o3;
    float u1x = o2 - dt * e0x, u1y = o3 - dt * e0y;
    float n1 = 1.0f / sqrtf(u1x * u1x + u1y * u1y);
    float e1x = u1x * n1, e1y = u1y * n1;
    float det = e0x * e1y - e1x * e0y;

    float* po = outp + (size_t)(row0 + tid) * 4;
    po[0] = e0x * det;
    po[1] = e1x;
    po[2] = e0y * det;
    po[3] = e1y;
  }
}

// ---------------------------------------------------------------------------
extern "C" void kernel_launch(void* const* d_in, const int* in_sizes, int n_in,
                              void* d_out, int out_size) {
  (void)in_sizes; (void)n_in; (void)out_size;
  const float* images = (const float*)d_in[0];
  const float* angles = (const float*)d_in[1];
  const float* W1 = (const float*)d_in[2];
  const float* b1 = (const float*)d_in[3];
  const float* W2 = (const float*)d_in[4];
  const float* b2 = (const float*)d_in[5];
  const float* W3 = (const float*)d_in[6];
  const float* b3 = (const float*)d_in[7];
  const float* W4 = (const float*)d_in[8];
  const float* b4 = (const float*)d_in[9];
  float* outp = (float*)d_out;

  cudaFuncSetAttribute(mlp_mma_kernel, cudaFuncAttributeMaxDynamicSharedMemorySize,
                       SM_FLOATS * 4);

  topk_feat_kernel<<<NIMG, 256>>>(images, angles);
  prep_weights<<<KPAD, 96>>>(W1, W2, W3);
  mlp_mma_kernel<<<NIMG / 64, 256, SM_FLOATS * 4>>>(b1, b2, b3, W4, b4, outp);
}

// round 14
// speedup vs baseline: 2.3285x; 1.2528x over previous
#include <cuda_runtime.h>
#include <cuda_fp16.h>
#include <math.h>

#define NIMG 32768
#define KPAD 640
#define DIN  620

// ---- device scratch (allocation-free) ----
__device__ __align__(16) float g_feat[(size_t)NIMG * KPAD];
// W fp16 hi/lo, FRAGMENT-MAJOR for m16n8k16: [chunk][kg][nblk][lane][(b0,b1)] (b32) x2 halves
__device__ __align__(16) __half g_W1h16[20 * 1536 * 2];
__device__ __align__(16) __half g_W1l16[20 * 1536 * 2];
__device__ __align__(16) __half g_W2h16[3 * 1536 * 2];
__device__ __align__(16) __half g_W2l16[3 * 1536 * 2];
__device__ __align__(16) __half g_W3h16[3 * 1536 * 2];
__device__ __align__(16) __half g_W3l16[3 * 1536 * 2];

// ---- fp16 split helpers ----
// pack two scaled floats into fp16x2 hi and lo-residual words
__device__ __forceinline__ void split2(float x, float y, unsigned& hi, unsigned& lo) {
  __half hx = __float2half_rn(x);
  __half hy = __float2half_rn(y);
  __half lx = __float2half_rn(x - __half2float(hx));
  __half ly = __float2half_rn(y - __half2float(hy));
  __half2 ph = __halves2half2(hx, hy);
  __half2 pl = __halves2half2(lx, ly);
  hi = *(unsigned*)&ph;
  lo = *(unsigned*)&pl;
}

// D += A*B  (m16n8k16, fp16 inputs, f32 accum)
__device__ __forceinline__ void mma_f16(float* c, const unsigned* a,
                                        unsigned b0, unsigned b1) {
  asm volatile(
      "mma.sync.aligned.m16n8k16.row.col.f32.f16.f16.f32 "
      "{%0,%1,%2,%3}, {%4,%5,%6,%7}, {%8,%9}, {%0,%1,%2,%3};"
      : "+f"(c[0]), "+f"(c[1]), "+f"(c[2]), "+f"(c[3])
      : "r"(a[0]), "r"(a[1]), "r"(a[2]), "r"(a[3]), "r"(b0), "r"(b1));
}

__device__ __forceinline__ unsigned smem_u32(const void* p) {
  unsigned a;
  asm("{ .reg .u64 t; cvta.to.shared.u64 t, %1; cvt.u32.u64 %0, t; }" : "=r"(a) : "l"(p));
  return a;
}
__device__ __forceinline__ void cp16(unsigned dst, const void* src) {
  asm volatile("cp.async.ca.shared.global [%0], [%1], 16;" :: "r"(dst), "l"(src));
}
#define CP_COMMIT() asm volatile("cp.async.commit_group;" ::: "memory")
#define CP_WAIT0()  asm volatile("cp.async.wait_group 0;" ::: "memory")
#define CP_WAIT1()  asm volatile("cp.async.wait_group 1;" ::: "memory")

// ---------------------------------------------------------------------------
// Kernel A: per-image top-200 stable selection + feature build (R13 version)
// ---------------------------------------------------------------------------
__global__ __launch_bounds__(256) void topk_feat_kernel(
    const float* __restrict__ images, const float* __restrict__ angles) {
  __shared__ unsigned int hist[256];
  __shared__ unsigned int above[256];
  __shared__ unsigned int cursor[256];
  __shared__ unsigned long long bucketed[784];
  __shared__ unsigned int wtot[8];
  __shared__ unsigned int wsuf[8];
  __shared__ int sT;

  const int b = blockIdx.x;
  const int tid = threadIdx.x;
  const float* img = images + (size_t)b * 784;
  float* fo = g_feat + (size_t)b * KPAD;

  if (tid < 10) {
    float a = angles[(size_t)b * 10 + tid];
    float sn, cs;
    sincosf(a, &sn, &cs);
    fo[600 + 2 * tid] = cs;
    fo[601 + 2 * tid] = sn;
  } else if (tid < 30) {
    fo[620 + (tid - 10)] = 0.f;  // pad k = 620..639
  }

  hist[tid] = 0u;
  cursor[tid] = 0u;
  __syncthreads();

  float va[4];
  int qa[4];
  if (tid < 196) {
    float4 v4 = *(const float4*)(img + tid * 4);
    va[0] = v4.x; va[1] = v4.y; va[2] = v4.z; va[3] = v4.w;
#pragma unroll
    for (int j = 0; j < 4; j++) {
      qa[j] = (int)(va[j] * 256.0f);
      atomicAdd(&hist[qa[j]], 1u);
    }
  }
  __syncthreads();

  unsigned h = hist[tid];
  unsigned s = h;
#pragma unroll
  for (int d = 1; d < 32; d <<= 1) {
    unsigned o = __shfl_down_sync(0xffffffffu, s, d);
    if ((tid & 31) + d < 32) s += o;
  }
  if ((tid & 31) == 0) wtot[tid >> 5] = s;
  __syncthreads();
  if (tid < 8) {
    unsigned t = 0;
    for (int j = tid + 1; j < 8; j++) t += wtot[j];
    wsuf[tid] = t;
  }
  __syncthreads();
  {
    unsigned a = (s - h) + wsuf[tid >> 5];
    above[tid] = a;
    if (a < 200u && a + h >= 200u) sT = tid;
  }
  __syncthreads();
  const int T = sT;

  if (tid < 196) {
#pragma unroll
    for (int j = 0; j < 4; j++) {
      if (qa[j] >= T) {
        unsigned int pos = above[qa[j]] + atomicAdd(&cursor[qa[j]], 1u);
        bucketed[pos] = ((unsigned long long)__float_as_uint(va[j]) << 32) |
                        (unsigned int)(tid * 4 + j);
      }
    }
  }
  __syncthreads();

  const int ncand = (int)(above[T] + hist[T]);
  for (int sI = tid; sI < ncand; sI += 256) {
    unsigned long long e = bucketed[sI];
    unsigned int vb = (unsigned int)(e >> 32);
    unsigned int idx = (unsigned int)(e & 0xffffffffu);
    float v = __uint_as_float(vb);
    int q = (int)(v * 256.0f);
    int lo = (int)above[q];
    int hi = lo + (int)hist[q];
    int rank = lo;
    for (int m = lo; m < hi; m++) {
      if (m == sI) continue;
      unsigned long long me = bucketed[m];
      unsigned int mvb = (unsigned int)(me >> 32);
      unsigned int midx = (unsigned int)(me & 0xffffffffu);
      if (mvb > vb || (mvb == vb && midx < idx)) rank++;
    }
    if (rank < 200) {
      int r = (int)idx / 28;
      int c = (int)idx - r * 28;
      float cx = (c < 14) ? (float)(c - 14) : (float)(c - 13);
      float cy = (r < 14) ? (float)(14 - r) : (float)(13 - r);
      float vv = v;
      if (vv < 0.1f) { vv = 0.f; cx = 0.f; cy = 0.f; }
      fo[rank] = vv;
      fo[200 + 2 * rank] = cx;
      fo[201 + 2 * rank] = cy;
    }
  }
}

// ---------------------------------------------------------------------------
// Weight prep: fp16 hi/lo split (x512), fragment-major for m16n8k16
// element (k,n): ch=k/32, kk16=k%16, kg=(k%32)/16, breg=kk16/8, tg=(kk16%8)/2,
// pos=k%2, g=n%8, nblk=n/8
// ---------------------------------------------------------------------------
__global__ void prep_weights(const float* __restrict__ W1,
                             const float* __restrict__ W2,
                             const float* __restrict__ W3) {
  int k = blockIdx.x;   // 0..639
  int n = threadIdx.x;  // 0..95
  int ch = k >> 5;
  int kk = k & 31;
  int kg = kk >> 4;
  int kk16 = kk & 15;
  int breg = kk16 >> 3;
  int tg = (kk16 & 7) >> 1;
  int pos = kk16 & 1;
  int g = n & 7;
  int nblk = n >> 3;
  size_t idx = ((size_t)ch * 1536 + (size_t)(kg * 12 + nblk) * 64 +
                (g * 4 + tg) * 2 + breg) * 2 + pos;
  {
    float v = ((k < DIN) ? W1[(size_t)k * 96 + n] : 0.f) * 512.0f;
    __half hh = __float2half_rn(v);
    __half hl = __float2half_rn(v - __half2float(hh));
    g_W1h16[idx] = hh;
    g_W1l16[idx] = hl;
  }
  if (k < 96) {
    float v2 = W2[(size_t)k * 96 + n] * 512.0f;
    __half h2 = __float2half_rn(v2);
    g_W2h16[idx] = h2;
    g_W2l16[idx] = __float2half_rn(v2 - __half2float(h2));
    float v3 = W3[(size_t)k * 96 + n] * 512.0f;
    __half h3 = __float2half_rn(v3);
    g_W3h16[idx] = h3;
    g_W3l16[idx] = __float2half_rn(v3 - __half2float(h3));
  }
}

// ---------------------------------------------------------------------------
// Kernel B: 3-term split-fp16 mma.sync MLP (m16n8k16), ping-pong W buffers
// ---------------------------------------------------------------------------
#define SBH0 0        // 1536 b32
#define SBL0 1536
#define SBH1 3072
#define SBL1 4608
#define SAH  6144     // A hi fragment slab: 8 tiles x 132 = 1056
#define SAL  7200
#define SH   8256     // activations [64][100] f32
#define SM_FLOATS 14656  // 58624 bytes

__device__ __forceinline__ void issue_W(unsigned smb, int sbh, int sbl,
                                        const __half* __restrict__ Wh,
                                        const __half* __restrict__ Wl,
                                        int ch, int tid) {
#pragma unroll
  for (int i = 0; i < 2; i++) {
    int idx = tid + i * 256;  // float4 index 0..383
    if (idx < 384) {
      cp16(smb + (sbh + idx * 4) * 4, Wh + (size_t)ch * 3072 + idx * 8);
      cp16(smb + (sbl + idx * 4) * 4, Wl + (size_t)ch * 3072 + idx * 8);
    }
  }
}

__global__ __launch_bounds__(256) void mlp_mma_kernel(
    const float* __restrict__ b1, const float* __restrict__ b2,
    const float* __restrict__ b3, const float* __restrict__ W4,
    const float* __restrict__ b4, float* __restrict__ outp) {
  extern __shared__ float sm[];
  const unsigned smb = smem_u32(sm);
  const int tid = threadIdx.x;
  const int warp = tid >> 5;
  const int lane = tid & 31;
  const int g = lane >> 2;
  const int tg = lane & 3;
  const int nbase = (warp & 3) * 24;
  const int mbase = (warp >> 2) * 32;
  const int row0 = blockIdx.x * 64;
  const float INV = 1.0f / 131072.0f;  // undo A*256 x W*512

  // A staging coordinates: thread owns (row r, k-cols q*4..q*4+3)
  const int ar0 = tid >> 3, aq0 = tid & 7;
  const int ar1 = (tid + 256) >> 3, aq1 = (tid + 256) & 7;
  // fragment store base: ((kg*4+mb)*132) + ((g*4+tgb)*4) + khalf*2 + aidx
  const int seg0 = ((aq0 >> 2) * 4 + (ar0 >> 4)) * 132 +
                   ((ar0 & 7) * 4 + 2 * (aq0 & 1)) * 4 +
                   ((aq0 >> 1) & 1) * 2 + ((ar0 >> 3) & 1);
  const int seg1 = ((aq1 >> 2) * 4 + (ar1 >> 4)) * 132 +
                   ((ar1 & 7) * 4 + 2 * (aq1 & 1)) * 4 +
                   ((aq1 >> 1) & 1) * 2 + ((ar1 >> 3) & 1);

  float c[3][2][4];
#pragma unroll
  for (int nt = 0; nt < 3; nt++)
#pragma unroll
    for (int mt = 0; mt < 2; mt++)
#pragma unroll
      for (int f = 0; f < 4; f++) c[nt][mt][f] = 0.f;

  float4 pfA0 = *(const float4*)(g_feat + (size_t)(row0 + ar0) * KPAD + aq0 * 4);
  float4 pfA1 = *(const float4*)(g_feat + (size_t)(row0 + ar1) * KPAD + aq1 * 4);
  issue_W(smb, SBH0, SBL0, g_W1h16, g_W1l16, 0, tid);
  CP_COMMIT();

  // ================= layer 1: K = 640, 20 chunks of 32 =================
  for (int ch = 0; ch < 20; ch++) {
    const int sbh = (ch & 1) ? SBH1 : SBH0;
    const int sbl = (ch & 1) ? SBL1 : SBL0;
    const int nsbh = (ch & 1) ? SBH0 : SBH1;
    const int nsbl = (ch & 1) ? SBL0 : SBL1;
    __syncthreads();
    if (ch + 1 < 20) {
      issue_W(smb, nsbh, nsbl, g_W1h16, g_W1l16, ch + 1, tid);
      CP_COMMIT();
    }
    // A: split prefetched f32 quads (x256) -> packed fp16 fragment slabs
    {
      unsigned h01, l01, h23, l23;
      split2(pfA0.x * 256.f, pfA0.y * 256.f, h01, l01);
      split2(pfA0.z * 256.f, pfA0.w * 256.f, h23, l23);
      *(unsigned*)&sm[SAH + seg0] = h01;
      *(unsigned*)&sm[SAH + seg0 + 4] = h23;
      *(unsigned*)&sm[SAL + seg0] = l01;
      *(unsigned*)&sm[SAL + seg0 + 4] = l23;
      split2(pfA1.x * 256.f, pfA1.y * 256.f, h01, l01);
      split2(pfA1.z * 256.f, pfA1.w * 256.f, h23, l23);
      *(unsigned*)&sm[SAH + seg1] = h01;
      *(unsigned*)&sm[SAH + seg1 + 4] = h23;
      *(unsigned*)&sm[SAL + seg1] = l01;
      *(unsigned*)&sm[SAL + seg1 + 4] = l23;
    }
    if (ch + 1 < 20) {
      pfA0 = *(const float4*)(g_feat + (size_t)(row0 + ar0) * KPAD + (ch + 1) * 32 + aq0 * 4);
      pfA1 = *(const float4*)(g_feat + (size_t)(row0 + ar1) * KPAD + (ch + 1) * 32 + aq1 * 4);
      CP_WAIT1();
    } else {
      CP_WAIT0();
    }
    __syncthreads();

#pragma unroll
    for (int kg = 0; kg < 2; kg++) {
      float4 ahf[2], alf[2];
#pragma unroll
      for (int mt = 0; mt < 2; mt++) {
        int mb = (warp >> 2) * 2 + mt;
        int off = (kg * 4 + mb) * 132 + lane * 4;
        ahf[mt] = *(const float4*)(sm + SAH + off);
        alf[mt] = *(const float4*)(sm + SAL + off);
      }
#pragma unroll
      for (int nt = 0; nt < 3; nt++) {
        int nblk = (warp & 3) * 3 + nt;
        int boff = (kg * 12 + nblk) * 64 + lane * 2;
        float2 bh = *(const float2*)(sm + sbh + boff);
        float2 bl = *(const float2*)(sm + sbl + boff);
        unsigned b0h = __float_as_uint(bh.x), b1h = __float_as_uint(bh.y);
        unsigned b0l = __float_as_uint(bl.x), b1l = __float_as_uint(bl.y);
#pragma unroll
        for (int mt = 0; mt < 2; mt++) {
          mma_f16(c[nt][mt], (const unsigned*)&ahf[mt], b0h, b1h);
          mma_f16(c[nt][mt], (const unsigned*)&ahf[mt], b0l, b1l);
          mma_f16(c[nt][mt], (const unsigned*)&alf[mt], b0h, b1h);
        }
      }
    }
  }

  // layer-1 writeback: unscale + bias + relu -> sH
  __syncthreads();
#pragma unroll
  for (int nt = 0; nt < 3; nt++) {
#pragma unroll
    for (int mt = 0; mt < 2; mt++) {
      int col = nbase + nt * 8 + 2 * tg;
      int r0 = mbase + mt * 16 + g;
      float bb0 = __ldg(b1 + col), bb1 = __ldg(b1 + col + 1);
      sm[SH + r0 * 100 + col] = fmaxf(fmaf(c[nt][mt][0], INV, bb0), 0.f);
      sm[SH + r0 * 100 + col + 1] = fmaxf(fmaf(c[nt][mt][1], INV, bb1), 0.f);
      sm[SH + (r0 + 8) * 100 + col] = fmaxf(fmaf(c[nt][mt][2], INV, bb0), 0.f);
      sm[SH + (r0 + 8) * 100 + col + 1] = fmaxf(fmaf(c[nt][mt][3], INV, bb1), 0.f);
#pragma unroll
      for (int f = 0; f < 4; f++) c[nt][mt][f] = 0.f;
    }
  }
  __syncthreads();

  // ================= layers 2 & 3: K = 96, 3 chunks of 32 =================
#pragma unroll 1
  for (int L = 0; L < 2; L++) {
    const __half* Wh = L ? g_W3h16 : g_W2h16;
    const __half* Wl = L ? g_W3l16 : g_W2l16;
    const float* bias = L ? b3 : b2;

    issue_W(smb, SBH0, SBL0, Wh, Wl, 0, tid);
    CP_COMMIT();

#pragma unroll 1
    for (int ch = 0; ch < 3; ch++) {
      const int sbh = (ch & 1) ? SBH1 : SBH0;
      const int sbl = (ch & 1) ? SBL1 : SBL0;
      const int nsbh = (ch & 1) ? SBH0 : SBH1;
      const int nsbl = (ch & 1) ? SBL0 : SBL1;
      __syncthreads();
      if (ch + 1 < 3) {
        issue_W(smb, nsbh, nsbl, Wh, Wl, ch + 1, tid);
        CP_COMMIT();
        CP_WAIT1();
      } else {
        CP_WAIT0();
      }
      __syncthreads();

#pragma unroll
      for (int kg = 0; kg < 2; kg++) {
        int ka = ch * 32 + kg * 16;
        unsigned ah[2][4], al[2][4];
#pragma unroll
        for (int mt = 0; mt < 2; mt++) {
          int r = mbase + mt * 16 + g;
          const float* p0 = sm + SH + r * 100 + ka;
          const float* p1 = sm + SH + (r + 8) * 100 + ka;
          int c0 = 2 * tg, c1 = 2 * tg + 8;
          split2(p0[c0] * 256.f, p0[c0 + 1] * 256.f, ah[mt][0], al[mt][0]);
          split2(p1[c0] * 256.f, p1[c0 + 1] * 256.f, ah[mt][1], al[mt][1]);
          split2(p0[c1] * 256.f, p0[c1 + 1] * 256.f, ah[mt][2], al[mt][2]);
          split2(p1[c1] * 256.f, p1[c1 + 1] * 256.f, ah[mt][3], al[mt][3]);
        }
#pragma unroll
        for (int nt = 0; nt < 3; nt++) {
          int nblk = (warp & 3) * 3 + nt;
          int boff = (kg * 12 + nblk) * 64 + lane * 2;
          float2 bh = *(const float2*)(sm + sbh + boff);
          float2 bl = *(const float2*)(sm + sbl + boff);
          unsigned b0h = __float_as_uint(bh.x), b1h = __float_as_uint(bh.y);
          unsigned b0l = __float_as_uint(bl.x), b1l = __float_as_uint(bl.y);
#pragma unroll
          for (int mt = 0; mt < 2; mt++) {
            mma_f16(c[nt][mt], ah[mt], b0h, b1h);
            mma_f16(c[nt][mt], ah[mt], b0l, b1l);
            mma_f16(c[nt][mt], al[mt], b0h, b1h);
          }
        }
      }
    }

    // writeback (all reads of sH complete: C lives in regs)
    __syncthreads();
#pragma unroll
    for (int nt = 0; nt < 3; nt++) {
#pragma unroll
      for (int mt = 0; mt < 2; mt++) {
        int col = nbase + nt * 8 + 2 * tg;
        int r0 = mbase + mt * 16 + g;
        float bb0 = __ldg(bias + col), bb1 = __ldg(bias + col + 1);
        sm[SH + r0 * 100 + col] = fmaxf(fmaf(c[nt][mt][0], INV, bb0), 0.f);
        sm[SH + r0 * 100 + col + 1] = fmaxf(fmaf(c[nt][mt][1], INV, bb1), 0.f);
        sm[SH + (r0 + 8) * 100 + col] = fmaxf(fmaf(c[nt][mt][2], INV, bb0), 0.f);
        sm[SH + (r0 + 8) * 100 + col + 1] = fmaxf(fmaf(c[nt][mt][3], INV, bb1), 0.f);
#pragma unroll
        for (int f = 0; f < 4; f++) c[nt][mt][f] = 0.f;
      }
    }
    __syncthreads();
  }

  // ================= layer 4 (96 -> 4) + Gram-Schmidt =================
  if (tid < 64) {
    float o0 = 0.f, o1 = 0.f, o2 = 0.f, o3 = 0.f;
#pragma unroll 4
    for (int k = 0; k < 96; k++) {
      float hv = sm[SH + tid * 100 + k];
      float4 w = *(const float4*)(W4 + (size_t)k * 4);
      o0 = fmaf(hv, w.x, o0);
      o1 = fmaf(hv, w.y, o1);
      o2 = fmaf(hv, w.z, o2);
      o3 = fmaf(hv, w.w, o3);
    }
    float4 bv = *(const float4*)(b4);
    o0 += bv.x; o1 += bv.y; o2 += bv.z; o3 += bv.w;

    float n0 = 1.0f / sqrtf(o0 * o0 + o1 * o1);
    float e0x = o0 * n0, e0y = o1 * n0;
    float dt = e0x * o2 + e0y * o3;
    float u1x = o2 - dt * e0x, u1y = o3 - dt * e0y;
    float n1 = 1.0f / sqrtf(u1x * u1x + u1y * u1y);
    float e1x = u1x * n1, e1y = u1y * n1;
    float det = e0x * e1y - e1x * e0y;

    float* po = outp + (size_t)(row0 + tid) * 4;
    po[0] = e0x * det;
    po[1] = e1x;
    po[2] = e0y * det;
    po[3] = e1y;
  }
}

// ---------------------------------------------------------------------------
extern "C" void kernel_launch(void* const* d_in, const int* in_sizes, int n_in,
                              void* d_out, int out_size) {
  (void)in_sizes; (void)n_in; (void)out_size;
  const float* images = (const float*)d_in[0];
  const float* angles = (const float*)d_in[1];
  const float* W1 = (const float*)d_in[2];
  const float* b1 = (const float*)d_in[3];
  const float* W2 = (const float*)d_in[4];
  const float* b2 = (const float*)d_in[5];
  const float* W3 = (const float*)d_in[6];
  const float* b3 = (const float*)d_in[7];
  const float* W4 = (const float*)d_in[8];
  const float* b4 = (const float*)d_in[9];
  float* outp = (float*)d_out;

  cudaFuncSetAttribute(mlp_mma_kernel, cudaFuncAttributeMaxDynamicSharedMemorySize,
                       SM_FLOATS * 4);

  topk_feat_kernel<<<NIMG, 256>>>(images, angles);
  prep_weights<<<KPAD, 96>>>(W1, W2, W3);
  mlp_mma_kernel<<<NIMG / 64, 256, SM_FLOATS * 4>>>(b1, b2, b3, W4, b4, outp);
}

// round 15
// speedup vs baseline: 2.3383x; 1.0042x over previous
#include <cuda_runtime.h>
#include <cuda_fp16.h>
#include <math.h>

#define NIMG 32768
#define KPAD 640
#define DIN  620

// ---- device scratch (allocation-free) ----
__device__ __align__(16) float g_feat[(size_t)NIMG * KPAD];
__device__ __align__(16) __half g_W1h16[20 * 1536 * 2];
__device__ __align__(16) __half g_W1l16[20 * 1536 * 2];
__device__ __align__(16) __half g_W2h16[3 * 1536 * 2];
__device__ __align__(16) __half g_W2l16[3 * 1536 * 2];
__device__ __align__(16) __half g_W3h16[3 * 1536 * 2];
__device__ __align__(16) __half g_W3l16[3 * 1536 * 2];

// ---- fp16 split helpers ----
__device__ __forceinline__ void split2(float x, float y, unsigned& hi, unsigned& lo) {
  __half hx = __float2half_rn(x);
  __half hy = __float2half_rn(y);
  __half lx = __float2half_rn(x - __half2float(hx));
  __half ly = __float2half_rn(y - __half2float(hy));
  __half2 ph = __halves2half2(hx, hy);
  __half2 pl = __halves2half2(lx, ly);
  hi = *(unsigned*)&ph;
  lo = *(unsigned*)&pl;
}

__device__ __forceinline__ void mma_f16(float* c, const unsigned* a,
                                        unsigned b0, unsigned b1) {
  asm volatile(
      "mma.sync.aligned.m16n8k16.row.col.f32.f16.f16.f32 "
      "{%0,%1,%2,%3}, {%4,%5,%6,%7}, {%8,%9}, {%0,%1,%2,%3};"
      : "+f"(c[0]), "+f"(c[1]), "+f"(c[2]), "+f"(c[3])
      : "r"(a[0]), "r"(a[1]), "r"(a[2]), "r"(a[3]), "r"(b0), "r"(b1));
}

__device__ __forceinline__ unsigned smem_u32(const void* p) {
  unsigned a;
  asm("{ .reg .u64 t; cvta.to.shared.u64 t, %1; cvt.u32.u64 %0, t; }" : "=r"(a) : "l"(p));
  return a;
}
__device__ __forceinline__ void cp16(unsigned dst, const void* src) {
  asm volatile("cp.async.ca.shared.global [%0], [%1], 16;" :: "r"(dst), "l"(src));
}
#define CP_COMMIT() asm volatile("cp.async.commit_group;" ::: "memory")
#define CP_WAIT0()  asm volatile("cp.async.wait_group 0;" ::: "memory")
#define CP_WAIT1()  asm volatile("cp.async.wait_group 1;" ::: "memory")

// ---------------------------------------------------------------------------
// Kernel A: per-image top-200 stable selection + feature build.
// Fast path: histogram/scan only bins >= 128 (valid when count(v>=0.5) >= 200,
// ~13-sigma certain for uniform images); exact full-histogram fallback.
// ---------------------------------------------------------------------------
__global__ __launch_bounds__(256) void topk_feat_kernel(
    const float* __restrict__ images, const float* __restrict__ angles) {
  __shared__ unsigned int hist[256];
  __shared__ unsigned int above[256];
  __shared__ unsigned int cursor[256];
  __shared__ unsigned long long bucketed[784];
  __shared__ unsigned int wtot[8];
  __shared__ unsigned int wsuf[8];
  __shared__ int sT;
  __shared__ unsigned int sTotal;

  const int b = blockIdx.x;
  const int tid = threadIdx.x;
  const float* img = images + (size_t)b * 784;
  float* fo = g_feat + (size_t)b * KPAD;

  if (tid < 10) {
    float a = angles[(size_t)b * 10 + tid];
    float sn, cs;
    __sincosf(a, &sn, &cs);
    fo[600 + 2 * tid] = cs;
    fo[601 + 2 * tid] = sn;
  } else if (tid < 30) {
    fo[620 + (tid - 10)] = 0.f;  // pad k = 620..639
  }

  hist[tid] = 0u;
  cursor[tid] = 0u;
  __syncthreads();

  // Pass 1: 196 threads load float4; histogram only bins >= 128
  float va[4];
  int qa[4];
  if (tid < 196) {
    float4 v4 = *(const float4*)(img + tid * 4);
    va[0] = v4.x; va[1] = v4.y; va[2] = v4.z; va[3] = v4.w;
#pragma unroll
    for (int j = 0; j < 4; j++) {
      qa[j] = (int)(va[j] * 256.0f);
      if (qa[j] >= 128) atomicAdd(&hist[qa[j]], 1u);
    }
  }
  __syncthreads();

  // Pass 2 (fast): suffix scan over bins 128..255, threads 0..127
  if (tid < 128) {
    unsigned h = hist[128 + tid];
    unsigned s = h;
#pragma unroll
    for (int d = 1; d < 32; d <<= 1) {
      unsigned o = __shfl_down_sync(0xffffffffu, s, d);
      if ((tid & 31) + d < 32) s += o;
    }
    if ((tid & 31) == 0) wtot[tid >> 5] = s;
    __syncwarp();
    wtot[4 + (tid >> 5)] = h;  // stash h? no - keep h in reg; dummy to reuse? skip
    // (h, s kept in registers across the barrier via recompute below)
  }
  __syncthreads();
  if (tid < 4) {
    unsigned t = 0;
    for (int j = tid + 1; j < 4; j++) t += wtot[j];
    wsuf[tid] = t;
  }
  __syncthreads();
  if (tid < 128) {
    unsigned h = hist[128 + tid];
    unsigned s = h;
#pragma unroll
    for (int d = 1; d < 32; d <<= 1) {
      unsigned o = __shfl_down_sync(0xffffffffu, s, d);
      if ((tid & 31) + d < 32) s += o;
    }
    unsigned a = (s - h) + wsuf[tid >> 5];
    above[128 + tid] = a;
    if (a < 200u && a + h >= 200u) sT = 128 + tid;
    if (tid == 0) sTotal = a + h;  // count(q >= 128)
  }
  __syncthreads();

  // Fallback (exact, essentially never taken for uniform inputs)
  if (sTotal < 200u) {
    if (tid < 196) {
#pragma unroll
      for (int j = 0; j < 4; j++) {
        if (qa[j] < 128) atomicAdd(&hist[qa[j]], 1u);
      }
    }
    __syncthreads();
    unsigned h = hist[tid];
    unsigned s = h;
#pragma unroll
    for (int d = 1; d < 32; d <<= 1) {
      unsigned o = __shfl_down_sync(0xffffffffu, s, d);
      if ((tid & 31) + d < 32) s += o;
    }
    if ((tid & 31) == 0) wtot[tid >> 5] = s;
    __syncthreads();
    if (tid < 8) {
      unsigned t = 0;
      for (int j = tid + 1; j < 8; j++) t += wtot[j];
      wsuf[tid] = t;
    }
    __syncthreads();
    {
      unsigned a = (s - h) + wsuf[tid >> 5];
      above[tid] = a;
      if (a < 200u && a + h >= 200u) sT = tid;
    }
    __syncthreads();
  }
  const int T = sT;

  // Pass 3: scatter candidates (q >= T) into bucket-grouped slots
  if (tid < 196) {
#pragma unroll
    for (int j = 0; j < 4; j++) {
      if (qa[j] >= T) {
        unsigned int pos = above[qa[j]] + atomicAdd(&cursor[qa[j]], 1u);
        bucketed[pos] = ((unsigned long long)__float_as_uint(va[j]) << 32) |
                        (unsigned int)(tid * 4 + j);
      }
    }
  }
  __syncthreads();

  // Pass 4: exact stable rank; write features at rank
  const int ncand = (int)(above[T] + hist[T]);
  for (int sI = tid; sI < ncand; sI += 256) {
    unsigned long long e = bucketed[sI];
    unsigned int vb = (unsigned int)(e >> 32);
    unsigned int idx = (unsigned int)(e & 0xffffffffu);
    float v = __uint_as_float(vb);
    int q = (int)(v * 256.0f);
    int lo = (int)above[q];
    int hi = lo + (int)hist[q];
    int rank = lo;
    for (int m = lo; m < hi; m++) {
      if (m == sI) continue;
      unsigned long long me = bucketed[m];
      unsigned int mvb = (unsigned int)(me >> 32);
      unsigned int midx = (unsigned int)(me & 0xffffffffu);
      if (mvb > vb || (mvb == vb && midx < idx)) rank++;
    }
    if (rank < 200) {
      int r = (int)idx / 28;
      int c = (int)idx - r * 28;
      float cx = (c < 14) ? (float)(c - 14) : (float)(c - 13);
      float cy = (r < 14) ? (float)(14 - r) : (float)(13 - r);
      float vv = v;
      if (vv < 0.1f) { vv = 0.f; cx = 0.f; cy = 0.f; }
      fo[rank] = vv;
      *(float2*)(fo + 200 + 2 * rank) = make_float2(cx, cy);
    }
  }
}

// ---------------------------------------------------------------------------
// Weight prep: fp16 hi/lo split (x512), fragment-major for m16n8k16
// ---------------------------------------------------------------------------
__global__ void prep_weights(const float* __restrict__ W1,
                             const float* __restrict__ W2,
                             const float* __restrict__ W3) {
  int k = blockIdx.x;   // 0..639
  int n = threadIdx.x;  // 0..95
  int ch = k >> 5;
  int kk = k & 31;
  int kg = kk >> 4;
  int kk16 = kk & 15;
  int breg = kk16 >> 3;
  int tg = (kk16 & 7) >> 1;
  int pos = kk16 & 1;
  int g = n & 7;
  int nblk = n >> 3;
  size_t idx = ((size_t)ch * 1536 + (size_t)(kg * 12 + nblk) * 64 +
                (g * 4 + tg) * 2 + breg) * 2 + pos;
  {
    float v = ((k < DIN) ? W1[(size_t)k * 96 + n] : 0.f) * 512.0f;
    __half hh = __float2half_rn(v);
    __half hl = __float2half_rn(v - __half2float(hh));
    g_W1h16[idx] = hh;
    g_W1l16[idx] = hl;
  }
  if (k < 96) {
    float v2 = W2[(size_t)k * 96 + n] * 512.0f;
    __half h2 = __float2half_rn(v2);
    g_W2h16[idx] = h2;
    g_W2l16[idx] = __float2half_rn(v2 - __half2float(h2));
    float v3 = W3[(size_t)k * 96 + n] * 512.0f;
    __half h3 = __float2half_rn(v3);
    g_W3h16[idx] = h3;
    g_W3l16[idx] = __float2half_rn(v3 - __half2float(h3));
  }
}

// ---------------------------------------------------------------------------
// Kernel B: 3-term split-fp16 mma.sync MLP (m16n8k16), ping-pong W buffers
// ---------------------------------------------------------------------------
#define SBH0 0
#define SBL0 1536
#define SBH1 3072
#define SBL1 4608
#define SAH  6144
#define SAL  7200
#define SH   8256
#define SM_FLOATS 14656  // 58624 bytes

__device__ __forceinline__ void issue_W(unsigned smb, int sbh, int sbl,
                                        const __half* __restrict__ Wh,
                                        const __half* __restrict__ Wl,
                                        int ch, int tid) {
#pragma unroll
  for (int i = 0; i < 2; i++) {
    int idx = tid + i * 256;
    if (idx < 384) {
      cp16(smb + (sbh + idx * 4) * 4, Wh + (size_t)ch * 3072 + idx * 8);
      cp16(smb + (sbl + idx * 4) * 4, Wl + (size_t)ch * 3072 + idx * 8);
    }
  }
}

__global__ __launch_bounds__(256) void mlp_mma_kernel(
    const float* __restrict__ b1, const float* __restrict__ b2,
    const float* __restrict__ b3, const float* __restrict__ W4,
    const float* __restrict__ b4, float* __restrict__ outp) {
  extern __shared__ float sm[];
  const unsigned smb = smem_u32(sm);
  const int tid = threadIdx.x;
  const int warp = tid >> 5;
  const int lane = tid & 31;
  const int g = lane >> 2;
  const int tg = lane & 3;
  const int nbase = (warp & 3) * 24;
  const int mbase = (warp >> 2) * 32;
  const int row0 = blockIdx.x * 64;
  const float INV = 1.0f / 131072.0f;

  const int ar0 = tid >> 3, aq0 = tid & 7;
  const int ar1 = (tid + 256) >> 3, aq1 = (tid + 256) & 7;
  const int seg0 = ((aq0 >> 2) * 4 + (ar0 >> 4)) * 132 +
                   ((ar0 & 7) * 4 + 2 * (aq0 & 1)) * 4 +
                   ((aq0 >> 1) & 1) * 2 + ((ar0 >> 3) & 1);
  const int seg1 = ((aq1 >> 2) * 4 + (ar1 >> 4)) * 132 +
                   ((ar1 & 7) * 4 + 2 * (aq1 & 1)) * 4 +
                   ((aq1 >> 1) & 1) * 2 + ((ar1 >> 3) & 1);

  float c[3][2][4];
#pragma unroll
  for (int nt = 0; nt < 3; nt++)
#pragma unroll
    for (int mt = 0; mt < 2; mt++)
#pragma unroll
      for (int f = 0; f < 4; f++) c[nt][mt][f] = 0.f;

  float4 pfA0 = *(const float4*)(g_feat + (size_t)(row0 + ar0) * KPAD + aq0 * 4);
  float4 pfA1 = *(const float4*)(g_feat + (size_t)(row0 + ar1) * KPAD + aq1 * 4);
  issue_W(smb, SBH0, SBL0, g_W1h16, g_W1l16, 0, tid);
  CP_COMMIT();

  // ================= layer 1: K = 640, 20 chunks of 32 =================
  for (int ch = 0; ch < 20; ch++) {
    const int sbh = (ch & 1) ? SBH1 : SBH0;
    const int sbl = (ch & 1) ? SBL1 : SBL0;
    const int nsbh = (ch & 1) ? SBH0 : SBH1;
    const int nsbl = (ch & 1) ? SBL0 : SBL1;
    __syncthreads();
    if (ch + 1 < 20) {
      issue_W(smb, nsbh, nsbl, g_W1h16, g_W1l16, ch + 1, tid);
      CP_COMMIT();
    }
    {
      unsigned h01, l01, h23, l23;
      split2(pfA0.x * 256.f, pfA0.y * 256.f, h01, l01);
      split2(pfA0.z * 256.f, pfA0.w * 256.f, h23, l23);
      *(unsigned*)&sm[SAH + seg0] = h01;
      *(unsigned*)&sm[SAH + seg0 + 4] = h23;
      *(unsigned*)&sm[SAL + seg0] = l01;
      *(unsigned*)&sm[SAL + seg0 + 4] = l23;
      split2(pfA1.x * 256.f, pfA1.y * 256.f, h01, l01);
      split2(pfA1.z * 256.f, pfA1.w * 256.f, h23, l23);
      *(unsigned*)&sm[SAH + seg1] = h01;
      *(unsigned*)&sm[SAH + seg1 + 4] = h23;
      *(unsigned*)&sm[SAL + seg1] = l01;
      *(unsigned*)&sm[SAL + seg1 + 4] = l23;
    }
    if (ch + 1 < 20) {
      pfA0 = *(const float4*)(g_feat + (size_t)(row0 + ar0) * KPAD + (ch + 1) * 32 + aq0 * 4);
      pfA1 = *(const float4*)(g_feat + (size_t)(row0 + ar1) * KPAD + (ch + 1) * 32 + aq1 * 4);
      CP_WAIT1();
    } else {
      CP_WAIT0();
    }
    __syncthreads();

#pragma unroll
    for (int kg = 0; kg < 2; kg++) {
      float4 ahf[2], alf[2];
#pragma unroll
      for (int mt = 0; mt < 2; mt++) {
        int mb = (warp >> 2) * 2 + mt;
        int off = (kg * 4 + mb) * 132 + lane * 4;
        ahf[mt] = *(const float4*)(sm + SAH + off);
        alf[mt] = *(const float4*)(sm + SAL + off);
      }
#pragma unroll
      for (int nt = 0; nt < 3; nt++) {
        int nblk = (warp & 3) * 3 + nt;
        int boff = (kg * 12 + nblk) * 64 + lane * 2;
        float2 bh = *(const float2*)(sm + sbh + boff);
        float2 bl = *(const float2*)(sm + sbl + boff);
        unsigned b0h = __float_as_uint(bh.x), b1h = __float_as_uint(bh.y);
        unsigned b0l = __float_as_uint(bl.x), b1l = __float_as_uint(bl.y);
#pragma unroll
        for (int mt = 0; mt < 2; mt++) {
          mma_f16(c[nt][mt], (const unsigned*)&ahf[mt], b0h, b1h);
          mma_f16(c[nt][mt], (const unsigned*)&ahf[mt], b0l, b1l);
          mma_f16(c[nt][mt], (const unsigned*)&alf[mt], b0h, b1h);
        }
      }
    }
  }

  // layer-1 writeback: unscale + bias + relu -> sH
  __syncthreads();
#pragma unroll
  for (int nt = 0; nt < 3; nt++) {
#pragma unroll
    for (int mt = 0; mt < 2; mt++) {
      int col = nbase + nt * 8 + 2 * tg;
      int r0 = mbase + mt * 16 + g;
      float bb0 = __ldg(b1 + col), bb1 = __ldg(b1 + col + 1);
      sm[SH + r0 * 100 + col] = fmaxf(fmaf(c[nt][mt][0], INV, bb0), 0.f);
      sm[SH + r0 * 100 + col + 1] = fmaxf(fmaf(c[nt][mt][1], INV, bb1), 0.f);
      sm[SH + (r0 + 8) * 100 + col] = fmaxf(fmaf(c[nt][mt][2], INV, bb0), 0.f);
      sm[SH + (r0 + 8) * 100 + col + 1] = fmaxf(fmaf(c[nt][mt][3], INV, bb1), 0.f);
#pragma unroll
      for (int f = 0; f < 4; f++) c[nt][mt][f] = 0.f;
    }
  }
  __syncthreads();

  // ================= layers 2 & 3: K = 96, 3 chunks of 32 =================
#pragma unroll 1
  for (int L = 0; L < 2; L++) {
    const __half* Wh = L ? g_W3h16 : g_W2h16;
    const __half* Wl = L ? g_W3l16 : g_W2l16;
    const float* bias = L ? b3 : b2;

    issue_W(smb, SBH0, SBL0, Wh, Wl, 0, tid);
    CP_COMMIT();

#pragma unroll 1
    for (int ch = 0; ch < 3; ch++) {
      const int sbh = (ch & 1) ? SBH1 : SBH0;
      const int sbl = (ch & 1) ? SBL1 : SBL0;
      const int nsbh = (ch & 1) ? SBH0 : SBH1;
      const int nsbl = (ch & 1) ? SBL0 : SBL1;
      __syncthreads();
      if (ch + 1 < 3) {
        issue_W(smb, nsbh, nsbl, Wh, Wl, ch + 1, tid);
        CP_COMMIT();
        CP_WAIT1();
      } else {
        CP_WAIT0();
      }
      __syncthreads();

#pragma unroll
      for (int kg = 0; kg < 2; kg++) {
        int ka = ch * 32 + kg * 16;
        unsigned ah[2][4], al[2][4];
#pragma unroll
        for (int mt = 0; mt < 2; mt++) {
          int r = mbase + mt * 16 + g;
          const float* p0 = sm + SH + r * 100 + ka;
          const float* p1 = sm + SH + (r + 8) * 100 + ka;
          int c0 = 2 * tg, c1 = 2 * tg + 8;
          split2(p0[c0] * 256.f, p0[c0 + 1] * 256.f, ah[mt][0], al[mt][0]);
          split2(p1[c0] * 256.f, p1[c0 + 1] * 256.f, ah[mt][1], al[mt][1]);
          split2(p0[c1] * 256.f, p0[c1 + 1] * 256.f, ah[mt][2], al[mt][2]);
          split2(p1[c1] * 256.f, p1[c1 + 1] * 256.f, ah[mt][3], al[mt][3]);
        }
#pragma unroll
        for (int nt = 0; nt < 3; nt++) {
          int nblk = (warp & 3) * 3 + nt;
          int boff = (kg * 12 + nblk) * 64 + lane * 2;
          float2 bh = *(const float2*)(sm + sbh + boff);
          float2 bl = *(const float2*)(sm + sbl + boff);
          unsigned b0h = __float_as_uint(bh.x), b1h = __float_as_uint(bh.y);
          unsigned b0l = __float_as_uint(bl.x), b1l = __float_as_uint(bl.y);
#pragma unroll
          for (int mt = 0; mt < 2; mt++) {
            mma_f16(c[nt][mt], ah[mt], b0h, b1h);
            mma_f16(c[nt][mt], ah[mt], b0l, b1l);
            mma_f16(c[nt][mt], al[mt], b0h, b1h);
          }
        }
      }
    }

    __syncthreads();
#pragma unroll
    for (int nt = 0; nt < 3; nt++) {
#pragma unroll
      for (int mt = 0; mt < 2; mt++) {
        int col = nbase + nt * 8 + 2 * tg;
        int r0 = mbase + mt * 16 + g;
        float bb0 = __ldg(bias + col), bb1 = __ldg(bias + col + 1);
        sm[SH + r0 * 100 + col] = fmaxf(fmaf(c[nt][mt][0], INV, bb0), 0.f);
        sm[SH + r0 * 100 + col + 1] = fmaxf(fmaf(c[nt][mt][1], INV, bb1), 0.f);
        sm[SH + (r0 + 8) * 100 + col] = fmaxf(fmaf(c[nt][mt][2], INV, bb0), 0.f);
        sm[SH + (r0 + 8) * 100 + col + 1] = fmaxf(fmaf(c[nt][mt][3], INV, bb1), 0.f);
#pragma unroll
        for (int f = 0; f < 4; f++) c[nt][mt][f] = 0.f;
      }
    }
    __syncthreads();
  }

  // ================= layer 4 (96 -> 4) + Gram-Schmidt =================
  if (tid < 64) {
    float o0 = 0.f, o1 = 0.f, o2 = 0.f, o3 = 0.f;
#pragma unroll 4
    for (int k = 0; k < 96; k++) {
      float hv = sm[SH + tid * 100 + k];
      float4 w = *(const float4*)(W4 + (size_t)k * 4);
      o0 = fmaf(hv, w.x, o0);
      o1 = fmaf(hv, w.y, o1);
      o2 = fmaf(hv, w.z, o2);
      o3 = fmaf(hv, w.w, o3);
    }
    float4 bv = *(const float4*)(b4);
    o0 += bv.x; o1 += bv.y; o2 += bv.z; o3 += bv.w;

    float n0 = 1.0f / sqrtf(o0 * o0 + o1 * o1);
    float e0x = o0 * n0, e0y = o1 * n0;
    float dt = e0x * o2 + e0y * o3;
    float u1x = o2 - dt * e0x, u1y = o3 - dt * e0y;
    float n1 = 1.0f / sqrtf(u1x * u1x + u1y * u1y);
    float e1x = u1x * n1, e1y = u1y * n1;
    float det = e0x * e1y - e1x * e0y;

    float* po = outp + (size_t)(row0 + tid) * 4;
    po[0] = e0x * det;
    po[1] = e1x;
    po[2] = e0y * det;
    po[3] = e1y;
  }
}

// ---------------------------------------------------------------------------
extern "C" void kernel_launch(void* const* d_in, const int* in_sizes, int n_in,
                              void* d_out, int out_size) {
  (void)in_sizes; (void)n_in; (void)out_size;
  const float* images = (const float*)d_in[0];
  const float* angles = (const float*)d_in[1];
  const float* W1 = (const float*)d_in[2];
  const float* b1 = (const float*)d_in[3];
  const float* W2 = (const float*)d_in[4];
  const float* b2 = (const float*)d_in[5];
  const float* W3 = (const float*)d_in[6];
  const float* b3 = (const float*)d_in[7];
  const float* W4 = (const float*)d_in[8];
  const float* b4 = (const float*)d_in[9];
  float* outp = (float*)d_out;

  cudaFuncSetAttribute(mlp_mma_kernel, cudaFuncAttributeMaxDynamicSharedMemorySize,
                       SM_FLOATS * 4);

  topk_feat_kernel<<<NIMG, 256>>>(images, angles);
  prep_weights<<<KPAD, 96>>>(W1, W2, W3);
  mlp_mma_kernel<<<NIMG / 64, 256, SM_FLOATS * 4>>>(b1, b2, b3, W4, b4, outp);
}

// round 16
// speedup vs baseline: 2.5921x; 1.1086x over previous
#include <cuda_runtime.h>
#include <cuda_fp16.h>
#include <math.h>

#define NIMG 32768
#define KPAD 640
#define DIN  620

// ---- device scratch (allocation-free) ----
__device__ __align__(16) float g_feat[(size_t)NIMG * KPAD];
__device__ __align__(16) __half g_W1h16[20 * 1536 * 2];
__device__ __align__(16) __half g_W1l16[20 * 1536 * 2];
__device__ __align__(16) __half g_W2h16[3 * 1536 * 2];
__device__ __align__(16) __half g_W2l16[3 * 1536 * 2];
__device__ __align__(16) __half g_W3h16[3 * 1536 * 2];
__device__ __align__(16) __half g_W3l16[3 * 1536 * 2];

// ---- fp16 split helpers ----
__device__ __forceinline__ void split2(float x, float y, unsigned& hi, unsigned& lo) {
  __half hx = __float2half_rn(x);
  __half hy = __float2half_rn(y);
  __half lx = __float2half_rn(x - __half2float(hx));
  __half ly = __float2half_rn(y - __half2float(hy));
  __half2 ph = __halves2half2(hx, hy);
  __half2 pl = __halves2half2(lx, ly);
  hi = *(unsigned*)&ph;
  lo = *(unsigned*)&pl;
}

__device__ __forceinline__ void mma_f16(float* c, const unsigned* a,
                                        unsigned b0, unsigned b1) {
  asm volatile(
      "mma.sync.aligned.m16n8k16.row.col.f32.f16.f16.f32 "
      "{%0,%1,%2,%3}, {%4,%5,%6,%7}, {%8,%9}, {%0,%1,%2,%3};"
      : "+f"(c[0]), "+f"(c[1]), "+f"(c[2]), "+f"(c[3])
      : "r"(a[0]), "r"(a[1]), "r"(a[2]), "r"(a[3]), "r"(b0), "r"(b1));
}

__device__ __forceinline__ unsigned smem_u32(const void* p) {
  unsigned a;
  asm("{ .reg .u64 t; cvta.to.shared.u64 t, %1; cvt.u32.u64 %0, t; }" : "=r"(a) : "l"(p));
  return a;
}
__device__ __forceinline__ void cp16(unsigned dst, const void* src) {
  asm volatile("cp.async.ca.shared.global [%0], [%1], 16;" :: "r"(dst), "l"(src));
}
#define CP_COMMIT() asm volatile("cp.async.commit_group;" ::: "memory")
#define CP_WAIT0()  asm volatile("cp.async.wait_group 0;" ::: "memory")
#define CP_WAIT1()  asm volatile("cp.async.wait_group 1;" ::: "memory")

// ---------------------------------------------------------------------------
// Kernel A: per-image top-200 stable selection + feature build.
// Candidates stored as monotone u64 keys: (vbits<<32)|(~idx) so the stable
// descending rank is a single 64-bit compare. Fast path scans bins >= 128
// only (count(v>=0.5) >= 200 w.h.p.); exact full fallback otherwise.
// ---------------------------------------------------------------------------
__global__ __launch_bounds__(256) void topk_feat_kernel(
    const float* __restrict__ images, const float* __restrict__ angles) {
  __shared__ unsigned int hist[256];
  __shared__ unsigned int above[256];
  __shared__ unsigned int cursor[256];
  __shared__ unsigned long long bucketed[784];
  __shared__ unsigned int wtot[8];
  __shared__ unsigned int wsuf[8];
  __shared__ int sT;
  __shared__ unsigned int sTotal;

  const int b = blockIdx.x;
  const int tid = threadIdx.x;
  const float* img = images + (size_t)b * 784;
  float* fo = g_feat + (size_t)b * KPAD;

  if (tid < 10) {
    float a = angles[(size_t)b * 10 + tid];
    float sn, cs;
    __sincosf(a, &sn, &cs);
    fo[600 + 2 * tid] = cs;
    fo[601 + 2 * tid] = sn;
  } else if (tid < 30) {
    fo[620 + (tid - 10)] = 0.f;  // pad k = 620..639
  }

  hist[tid] = 0u;
  cursor[tid] = 0u;
  __syncthreads();

  // Pass 1: 196 threads load float4; histogram bins >= 128 only
  float va[4];
  int qa[4];
  if (tid < 196) {
    float4 v4 = *(const float4*)(img + tid * 4);
    va[0] = v4.x; va[1] = v4.y; va[2] = v4.z; va[3] = v4.w;
#pragma unroll
    for (int j = 0; j < 4; j++) {
      qa[j] = (int)(va[j] * 256.0f);
      if (qa[j] >= 128) atomicAdd(&hist[qa[j]], 1u);
    }
  }
  __syncthreads();

  // Pass 2 (fast): single suffix scan over bins 128..255 (h,s stay in regs)
  unsigned h = 0, s = 0;
  if (tid < 128) {
    h = hist[128 + tid];
    s = h;
#pragma unroll
    for (int d = 1; d < 32; d <<= 1) {
      unsigned o = __shfl_down_sync(0xffffffffu, s, d);
      if ((tid & 31) + d < 32) s += o;
    }
    if ((tid & 31) == 0) wtot[tid >> 5] = s;
  }
  __syncthreads();
  if (tid < 4) {
    unsigned t = 0;
    for (int j = tid + 1; j < 4; j++) t += wtot[j];
    wsuf[tid] = t;
  }
  __syncthreads();
  if (tid < 128) {
    unsigned a = (s - h) + wsuf[tid >> 5];
    above[128 + tid] = a;
    if (a < 200u && a + h >= 200u) sT = 128 + tid;
    if (tid == 0) sTotal = a + h;  // count(q >= 128)
  }
  __syncthreads();

  // Exact fallback (essentially never taken for uniform inputs)
  if (sTotal < 200u) {
    if (tid < 196) {
#pragma unroll
      for (int j = 0; j < 4; j++) {
        if (qa[j] < 128) atomicAdd(&hist[qa[j]], 1u);
      }
    }
    __syncthreads();
    unsigned hf = hist[tid];
    unsigned sf = hf;
#pragma unroll
    for (int d = 1; d < 32; d <<= 1) {
      unsigned o = __shfl_down_sync(0xffffffffu, sf, d);
      if ((tid & 31) + d < 32) sf += o;
    }
    if ((tid & 31) == 0) wtot[tid >> 5] = sf;
    __syncthreads();
    if (tid < 8) {
      unsigned t = 0;
      for (int j = tid + 1; j < 8; j++) t += wtot[j];
      wsuf[tid] = t;
    }
    __syncthreads();
    {
      unsigned a = (sf - hf) + wsuf[tid >> 5];
      above[tid] = a;
      if (a < 200u && a + hf >= 200u) sT = tid;
    }
    __syncthreads();
  }
  const int T = sT;

  // Pass 3: scatter candidate keys (q >= T) into bucket-grouped slots.
  // key = (vbits << 32) | (~idx): strictly larger key <=> strictly earlier rank.
  if (tid < 196) {
#pragma unroll
    for (int j = 0; j < 4; j++) {
      if (qa[j] >= T) {
        unsigned int pos = above[qa[j]] + atomicAdd(&cursor[qa[j]], 1u);
        bucketed[pos] = ((unsigned long long)__float_as_uint(va[j]) << 32) |
                        (unsigned int)(0xFFFFFFFFu - (unsigned)(tid * 4 + j));
      }
    }
  }
  __syncthreads();

  // Pass 4: exact stable rank via single u64 compare per bucket-mate
  const int ncand = (int)(above[T] + hist[T]);
  for (int sI = tid; sI < ncand; sI += 256) {
    unsigned long long key = bucketed[sI];
    unsigned int vb = (unsigned int)(key >> 32);
    unsigned int idx = 0xFFFFFFFFu - (unsigned int)(key & 0xFFFFFFFFu);
    float v = __uint_as_float(vb);
    int q = (int)(v * 256.0f);
    int lo = (int)above[q];
    int hi = lo + (int)hist[q];
    int rank = lo;
    for (int m = lo; m < hi; m++) {
      if (bucketed[m] > key) rank++;
    }
    if (rank < 200) {
      int r = (int)idx / 28;
      int c = (int)idx - r * 28;
      float cx = (c < 14) ? (float)(c - 14) : (float)(c - 13);
      float cy = (r < 14) ? (float)(14 - r) : (float)(13 - r);
      float vv = v;
      if (vv < 0.1f) { vv = 0.f; cx = 0.f; cy = 0.f; }
      fo[rank] = vv;
      *(float2*)(fo + 200 + 2 * rank) = make_float2(cx, cy);
    }
  }
}

// ---------------------------------------------------------------------------
// Weight prep: fp16 hi/lo split (x512), fragment-major for m16n8k16
// ---------------------------------------------------------------------------
__global__ void prep_weights(const float* __restrict__ W1,
                             const float* __restrict__ W2,
                             const float* __restrict__ W3) {
  int k = blockIdx.x;   // 0..639
  int n = threadIdx.x;  // 0..95
  int ch = k >> 5;
  int kk = k & 31;
  int kg = kk >> 4;
  int kk16 = kk & 15;
  int breg = kk16 >> 3;
  int tg = (kk16 & 7) >> 1;
  int pos = kk16 & 1;
  int g = n & 7;
  int nblk = n >> 3;
  size_t idx = ((size_t)ch * 1536 + (size_t)(kg * 12 + nblk) * 64 +
                (g * 4 + tg) * 2 + breg) * 2 + pos;
  {
    float v = ((k < DIN) ? W1[(size_t)k * 96 + n] : 0.f) * 512.0f;
    __half hh = __float2half_rn(v);
    __half hl = __float2half_rn(v - __half2float(hh));
    g_W1h16[idx] = hh;
    g_W1l16[idx] = hl;
  }
  if (k < 96) {
    float v2 = W2[(size_t)k * 96 + n] * 512.0f;
    __half h2 = __float2half_rn(v2);
    g_W2h16[idx] = h2;
    g_W2l16[idx] = __float2half_rn(v2 - __half2float(h2));
    float v3 = W3[(size_t)k * 96 + n] * 512.0f;
    __half h3 = __float2half_rn(v3);
    g_W3h16[idx] = h3;
    g_W3l16[idx] = __float2half_rn(v3 - __half2float(h3));
  }
}

// ---------------------------------------------------------------------------
// Kernel B: 3-term split-fp16 mma.sync MLP (m16n8k16), ping-pong W buffers
// ---------------------------------------------------------------------------
#define SBH0 0
#define SBL0 1536
#define SBH1 3072
#define SBL1 4608
#define SAH  6144
#define SAL  7200
#define SH   8256
#define SM_FLOATS 14656  // 58624 bytes

__device__ __forceinline__ void issue_W(unsigned smb, int sbh, int sbl,
                                        const __half* __restrict__ Wh,
                                        const __half* __restrict__ Wl,
                                        int ch, int tid) {
#pragma unroll
  for (int i = 0; i < 2; i++) {
    int idx = tid + i * 256;
    if (idx < 384) {
      cp16(smb + (sbh + idx * 4) * 4, Wh + (size_t)ch * 3072 + idx * 8);
      cp16(smb + (sbl + idx * 4) * 4, Wl + (size_t)ch * 3072 + idx * 8);
    }
  }
}

__global__ __launch_bounds__(256) void mlp_mma_kernel(
    const float* __restrict__ b1, const float* __restrict__ b2,
    const float* __restrict__ b3, const float* __restrict__ W4,
    const float* __restrict__ b4, float* __restrict__ outp) {
  extern __shared__ float sm[];
  const unsigned smb = smem_u32(sm);
  const int tid = threadIdx.x;
  const int warp = tid >> 5;
  const int lane = tid & 31;
  const int g = lane >> 2;
  const int tg = lane & 3;
  const int nbase = (warp & 3) * 24;
  const int mbase = (warp >> 2) * 32;
  const int row0 = blockIdx.x * 64;
  const float INV = 1.0f / 131072.0f;

  const int ar0 = tid >> 3, aq0 = tid & 7;
  const int ar1 = (tid + 256) >> 3, aq1 = (tid + 256) & 7;
  const int seg0 = ((aq0 >> 2) * 4 + (ar0 >> 4)) * 132 +
                   ((ar0 & 7) * 4 + 2 * (aq0 & 1)) * 4 +
                   ((aq0 >> 1) & 1) * 2 + ((ar0 >> 3) & 1);
  const int seg1 = ((aq1 >> 2) * 4 + (ar1 >> 4)) * 132 +
                   ((ar1 & 7) * 4 + 2 * (aq1 & 1)) * 4 +
                   ((aq1 >> 1) & 1) * 2 + ((ar1 >> 3) & 1);

  float c[3][2][4];
#pragma unroll
  for (int nt = 0; nt < 3; nt++)
#pragma unroll
    for (int mt = 0; mt < 2; mt++)
#pragma unroll
      for (int f = 0; f < 4; f++) c[nt][mt][f] = 0.f;

  float4 pfA0 = *(const float4*)(g_feat + (size_t)(row0 + ar0) * KPAD + aq0 * 4);
  float4 pfA1 = *(const float4*)(g_feat + (size_t)(row0 + ar1) * KPAD + aq1 * 4);
  issue_W(smb, SBH0, SBL0, g_W1h16, g_W1l16, 0, tid);
  CP_COMMIT();

  // ================= layer 1: K = 640, 20 chunks of 32 =================
  for (int ch = 0; ch < 20; ch++) {
    const int sbh = (ch & 1) ? SBH1 : SBH0;
    const int sbl = (ch & 1) ? SBL1 : SBL0;
    const int nsbh = (ch & 1) ? SBH0 : SBH1;
    const int nsbl = (ch & 1) ? SBL0 : SBL1;
    __syncthreads();
    if (ch + 1 < 20) {
      issue_W(smb, nsbh, nsbl, g_W1h16, g_W1l16, ch + 1, tid);
      CP_COMMIT();
    }
    {
      unsigned h01, l01, h23, l23;
      split2(pfA0.x * 256.f, pfA0.y * 256.f, h01, l01);
      split2(pfA0.z * 256.f, pfA0.w * 256.f, h23, l23);
      *(unsigned*)&sm[SAH + seg0] = h01;
      *(unsigned*)&sm[SAH + seg0 + 4] = h23;
      *(unsigned*)&sm[SAL + seg0] = l01;
      *(unsigned*)&sm[SAL + seg0 + 4] = l23;
      split2(pfA1.x * 256.f, pfA1.y * 256.f, h01, l01);
      split2(pfA1.z * 256.f, pfA1.w * 256.f, h23, l23);
      *(unsigned*)&sm[SAH + seg1] = h01;
      *(unsigned*)&sm[SAH + seg1 + 4] = h23;
      *(unsigned*)&sm[SAL + seg1] = l01;
      *(unsigned*)&sm[SAL + seg1 + 4] = l23;
    }
    if (ch + 1 < 20) {
      pfA0 = *(const float4*)(g_feat + (size_t)(row0 + ar0) * KPAD + (ch + 1) * 32 + aq0 * 4);
      pfA1 = *(const float4*)(g_feat + (size_t)(row0 + ar1) * KPAD + (ch + 1) * 32 + aq1 * 4);
      CP_WAIT1();
    } else {
      CP_WAIT0();
    }
    __syncthreads();

#pragma unroll
    for (int kg = 0; kg < 2; kg++) {
      float4 ahf[2], alf[2];
#pragma unroll
      for (int mt = 0; mt < 2; mt++) {
        int mb = (warp >> 2) * 2 + mt;
        int off = (kg * 4 + mb) * 132 + lane * 4;
        ahf[mt] = *(const float4*)(sm + SAH + off);
        alf[mt] = *(const float4*)(sm + SAL + off);
      }
#pragma unroll
      for (int nt = 0; nt < 3; nt++) {
        int nblk = (warp & 3) * 3 + nt;
        int boff = (kg * 12 + nblk) * 64 + lane * 2;
        float2 bh = *(const float2*)(sm + sbh + boff);
        float2 bl = *(const float2*)(sm + sbl + boff);
        unsigned b0h = __float_as_uint(bh.x), b1h = __float_as_uint(bh.y);
        unsigned b0l = __float_as_uint(bl.x), b1l = __float_as_uint(bl.y);
#pragma unroll
        for (int mt = 0; mt < 2; mt++) {
          mma_f16(c[nt][mt], (const unsigned*)&ahf[mt], b0h, b1h);
          mma_f16(c[nt][mt], (const unsigned*)&ahf[mt], b0l, b1l);
          mma_f16(c[nt][mt], (const unsigned*)&alf[mt], b0h, b1h);
        }
      }
    }
  }

  // layer-1 writeback: unscale + bias + relu -> sH
  __syncthreads();
#pragma unroll
  for (int nt = 0; nt < 3; nt++) {
#pragma unroll
    for (int mt = 0; mt < 2; mt++) {
      int col = nbase + nt * 8 + 2 * tg;
      int r0 = mbase + mt * 16 + g;
      float bb0 = __ldg(b1 + col), bb1 = __ldg(b1 + col + 1);
      sm[SH + r0 * 100 + col] = fmaxf(fmaf(c[nt][mt][0], INV, bb0), 0.f);
      sm[SH + r0 * 100 + col + 1] = fmaxf(fmaf(c[nt][mt][1], INV, bb1), 0.f);
      sm[SH + (r0 + 8) * 100 + col] = fmaxf(fmaf(c[nt][mt][2], INV, bb0), 0.f);
      sm[SH + (r0 + 8) * 100 + col + 1] = fmaxf(fmaf(c[nt][mt][3], INV, bb1), 0.f);
#pragma unroll
      for (int f = 0; f < 4; f++) c[nt][mt][f] = 0.f;
    }
  }
  __syncthreads();

  // ================= layers 2 & 3: K = 96, 3 chunks of 32 =================
#pragma unroll 1
  for (int L = 0; L < 2; L++) {
    const __half* Wh = L ? g_W3h16 : g_W2h16;
    const __half* Wl = L ? g_W3l16 : g_W2l16;
    const float* bias = L ? b3 : b2;

    issue_W(smb, SBH0, SBL0, Wh, Wl, 0, tid);
    CP_COMMIT();

#pragma unroll 1
    for (int ch = 0; ch < 3; ch++) {
      const int sbh = (ch & 1) ? SBH1 : SBH0;
      const int sbl = (ch & 1) ? SBL1 : SBL0;
      const int nsbh = (ch & 1) ? SBH0 : SBH1;
      const int nsbl = (ch & 1) ? SBL0 : SBL1;
      __syncthreads();
      if (ch + 1 < 3) {
        issue_W(smb, nsbh, nsbl, Wh, Wl, ch + 1, tid);
        CP_COMMIT();
        CP_WAIT1();
      } else {
        CP_WAIT0();
      }
      __syncthreads();

#pragma unroll
      for (int kg = 0; kg < 2; kg++) {
        int ka = ch * 32 + kg * 16;
        unsigned ah[2][4], al[2][4];
#pragma unroll
        for (int mt = 0; mt < 2; mt++) {
          int r = mbase + mt * 16 + g;
          const float* p0 = sm + SH + r * 100 + ka;
          const float* p1 = sm + SH + (r + 8) * 100 + ka;
          int c0 = 2 * tg, c1 = 2 * tg + 8;
          split2(p0[c0] * 256.f, p0[c0 + 1] * 256.f, ah[mt][0], al[mt][0]);
          split2(p1[c0] * 256.f, p1[c0 + 1] * 256.f, ah[mt][1], al[mt][1]);
          split2(p0[c1] * 256.f, p0[c1 + 1] * 256.f, ah[mt][2], al[mt][2]);
          split2(p1[c1] * 256.f, p1[c1 + 1] * 256.f, ah[mt][3], al[mt][3]);
        }
#pragma unroll
        for (int nt = 0; nt < 3; nt++) {
          int nblk = (warp & 3) * 3 + nt;
          int boff = (kg * 12 + nblk) * 64 + lane * 2;
          float2 bh = *(const float2*)(sm + sbh + boff);
          float2 bl = *(const float2*)(sm + sbl + boff);
          unsigned b0h = __float_as_uint(bh.x), b1h = __float_as_uint(bh.y);
          unsigned b0l = __float_as_uint(bl.x), b1l = __float_as_uint(bl.y);
#pragma unroll
          for (int mt = 0; mt < 2; mt++) {
            mma_f16(c[nt][mt], ah[mt], b0h, b1h);
            mma_f16(c[nt][mt], ah[mt], b0l, b1l);
            mma_f16(c[nt][mt], al[mt], b0h, b1h);
          }
        }
      }
    }

    __syncthreads();
#pragma unroll
    for (int nt = 0; nt < 3; nt++) {
#pragma unroll
      for (int mt = 0; mt < 2; mt++) {
        int col = nbase + nt * 8 + 2 * tg;
        int r0 = mbase + mt * 16 + g;
        float bb0 = __ldg(bias + col), bb1 = __ldg(bias + col + 1);
        sm[SH + r0 * 100 + col] = fmaxf(fmaf(c[nt][mt][0], INV, bb0), 0.f);
        sm[SH + r0 * 100 + col + 1] = fmaxf(fmaf(c[nt][mt][1], INV, bb1), 0.f);
        sm[SH + (r0 + 8) * 100 + col] = fmaxf(fmaf(c[nt][mt][2], INV, bb0), 0.f);
        sm[SH + (r0 + 8) * 100 + col + 1] = fmaxf(fmaf(c[nt][mt][3], INV, bb1), 0.f);
#pragma unroll
        for (int f = 0; f < 4; f++) c[nt][mt][f] = 0.f;
      }
    }
    __syncthreads();
  }

  // ================= layer 4 (96 -> 4) + Gram-Schmidt =================
  if (tid < 64) {
    float o0 = 0.f, o1 = 0.f, o2 = 0.f, o3 = 0.f;
#pragma unroll 4
    for (int k = 0; k < 96; k++) {
      float hv = sm[SH + tid * 100 + k];
      float4 w = *(const float4*)(W4 + (size_t)k * 4);
      o0 = fmaf(hv, w.x, o0);
      o1 = fmaf(hv, w.y, o1);
      o2 = fmaf(hv, w.z, o2);
      o3 = fmaf(hv, w.w, o3);
    }
    float4 bv = *(const float4*)(b4);
    o0 += bv.x; o1 += bv.y; o2 += bv.z; o3 += bv.w;

    float n0 = 1.0f / sqrtf(o0 * o0 + o1 * o1);
    float e0x = o0 * n0, e0y = o1 * n0;
    float dt = e0x * o2 + e0y * o3;
    float u1x = o2 - dt * e0x, u1y = o3 - dt * e0y;
    float n1 = 1.0f / sqrtf(u1x * u1x + u1y * u1y);
    float e1x = u1x * n1, e1y = u1y * n1;
    float det = e0x * e1y - e1x * e0y;

    float* po = outp + (size_t)(row0 + tid) * 4;
    po[0] = e0x * det;
    po[1] = e1x;
    po[2] = e0y * det;
    po[3] = e1y;
  }
}

// ---------------------------------------------------------------------------
extern "C" void kernel_launch(void* const* d_in, const int* in_sizes, int n_in,
                              void* d_out, int out_size) {
  (void)in_sizes; (void)n_in; (void)out_size;
  const float* images = (const float*)d_in[0];
  const float* angles = (const float*)d_in[1];
  const float* W1 = (const float*)d_in[2];
  const float* b1 = (const float*)d_in[3];
  const float* W2 = (const float*)d_in[4];
  const float* b2 = (const float*)d_in[5];
  const float* W3 = (const float*)d_in[6];
  const float* b3 = (const float*)d_in[7];
  const float* W4 = (const float*)d_in[8];
  const float* b4 = (const float*)d_in[9];
  float* outp = (float*)d_out;

  cudaFuncSetAttribute(mlp_mma_kernel, cudaFuncAttributeMaxDynamicSharedMemorySize,
                       SM_FLOATS * 4);

  topk_feat_kernel<<<NIMG, 256>>>(images, angles);
  prep_weights<<<KPAD, 96>>>(W1, W2, W3);
  mlp_mma_kernel<<<NIMG / 64, 256, SM_FLOATS * 4>>>(b1, b2, b3, W4, b4, outp);
}